// round 1
// baseline (speedup 1.0000x reference)
#include <cuda_runtime.h>

#define C_DIM 1024
#define C3    3072
#define BB    2
#define TT    2048
#define HH    16
#define MTOT  4096   // BB*TT

// Scratch (static device allocations are the sanctioned workaround)
__device__ float g_qkv[(size_t)MTOT * C3];    // QKV activations, row = (b*T+t), col layout [Q|K|V]
__device__ float g_att[(size_t)MTOT * C_DIM]; // attention output in (B,T,C) layout

// ---------------------------------------------------------------------------
// SGEMM: C[M][N] = A[M][K] @ B[K][N] + bias[N].  128x128 tile, BK=8, 256 thr,
// 8x8 register micro-tiles. M,N multiples of 128; K multiple of 8.
// ---------------------------------------------------------------------------
__global__ __launch_bounds__(256) void sgemm_bias_k(
    const float* __restrict__ A, const float* __restrict__ Bm,
    const float* __restrict__ bias, float* __restrict__ Cc,
    int N, int K)
{
    __shared__ float As[8][132];   // pad 132: conflict-free transpose stores
    __shared__ float Bs[8][132];

    const int t  = threadIdx.x;
    const int tx = t & 15, ty = t >> 4;
    const int m0 = blockIdx.y << 7, n0 = blockIdx.x << 7;

    const int arow = t >> 1, apart = (t & 1) << 2;   // A: 128 rows x 8 cols
    const int brow = t >> 5, bcol = (t & 31) << 2;   // B: 8 rows x 128 cols

    const float* Aptr = A  + (size_t)(m0 + arow) * K + apart;
    const float* Bptr = Bm + (size_t)brow * N + n0 + bcol;

    float acc[8][8];
#pragma unroll
    for (int i = 0; i < 8; i++)
#pragma unroll
        for (int j = 0; j < 8; j++) acc[i][j] = 0.f;

    for (int k0 = 0; k0 < K; k0 += 8) {
        float4 av = *(const float4*)(Aptr + k0);
        float4 bv = *(const float4*)(Bptr + (size_t)k0 * N);
        As[apart + 0][arow] = av.x;
        As[apart + 1][arow] = av.y;
        As[apart + 2][arow] = av.z;
        As[apart + 3][arow] = av.w;
        *(float4*)&Bs[brow][bcol] = bv;
        __syncthreads();

#pragma unroll
        for (int kk = 0; kk < 8; kk++) {
            float a[8], b[8];
            *(float4*)(a)     = *(const float4*)&As[kk][ty * 8];
            *(float4*)(a + 4) = *(const float4*)&As[kk][ty * 8 + 4];
            *(float4*)(b)     = *(const float4*)&Bs[kk][tx * 8];
            *(float4*)(b + 4) = *(const float4*)&Bs[kk][tx * 8 + 4];
#pragma unroll
            for (int i = 0; i < 8; i++)
#pragma unroll
                for (int j = 0; j < 8; j++)
                    acc[i][j] = fmaf(a[i], b[j], acc[i][j]);
        }
        __syncthreads();
    }

#pragma unroll
    for (int i = 0; i < 8; i++) {
        const int m = m0 + ty * 8 + i;
#pragma unroll
        for (int hlf = 0; hlf < 2; hlf++) {
            const int n = n0 + tx * 8 + hlf * 4;
            float4 bv = *(const float4*)&bias[n];
            float4 cv;
            cv.x = acc[i][hlf * 4 + 0] + bv.x;
            cv.y = acc[i][hlf * 4 + 1] + bv.y;
            cv.z = acc[i][hlf * 4 + 2] + bv.z;
            cv.w = acc[i][hlf * 4 + 3] + bv.w;
            *(float4*)&Cc[(size_t)m * N + n] = cv;
        }
    }
}

// ---------------------------------------------------------------------------
// Causal flash attention, fp32. One block = one (b,h) and a 64-query tile.
// 256 threads; each thread owns a 4x4 S/P micro-tile and a 4x4 O micro-tile.
// Online softmax; K-tile and P-tile share one smem buffer (phase-separated).
// Dynamic smem = Qs[64][65] + KP[64][65] + Vs[64][64] = 49664 B.
// ---------------------------------------------------------------------------
#define SMEM_ATT ((64 * 65 * 2 + 64 * 64) * 4)

__global__ __launch_bounds__(256) void attn_k(const float* __restrict__ qkv,
                                              float* __restrict__ outp)
{
    extern __shared__ float sm[];
    float* Qs  = sm;               // [64][65], pre-scaled by 1/sqrt(Dh)
    float* KPs = sm + 64 * 65;     // [64][65], K-tile then P-tile
    float* Vs  = sm + 2 * 64 * 65; // [64][64]

    const int t  = threadIdx.x;
    const int qi = gridDim.x - 1 - blockIdx.x;  // heavy tiles first (wave packing)
    const int bh = blockIdx.y;
    const int b  = bh >> 4, h = bh & 15;
    const int r0 = (t >> 4) << 2;   // 4 query rows
    const int c0 = (t & 15) << 2;   // 4 key cols / 4 out dims
    const int qbase = qi << 6;
    const size_t brow = (size_t)b * TT;

    // Load + pre-scale Q tile
    for (int idx = t; idx < 4096; idx += 256) {
        const int r = idx >> 6, k = idx & 63;
        Qs[r * 65 + k] = qkv[(brow + qbase + r) * C3 + h * 64 + k] * 0.125f;
    }

    float o[4][4];
    float mrow[4], lrow[4];
#pragma unroll
    for (int i = 0; i < 4; i++) {
        mrow[i] = -1e30f; lrow[i] = 0.f;
#pragma unroll
        for (int j = 0; j < 4; j++) o[i][j] = 0.f;
    }

    for (int j = 0; j <= qi; j++) {
        __syncthreads();  // prev PV reads done (also covers Q fill on iter 0)
        const int kb = j << 6;
        for (int idx = t; idx < 4096; idx += 256) {
            const int r = idx >> 6, k = idx & 63;
            const size_t g = (brow + kb + r) * C3 + h * 64 + k;
            KPs[r * 65 + k] = qkv[g + 1024];  // K
            Vs[r * 64 + k]  = qkv[g + 2048];  // V
        }
        __syncthreads();

        // S = Q * K^T   (4x4 micro-tile per thread)
        float s[4][4];
#pragma unroll
        for (int i = 0; i < 4; i++)
#pragma unroll
            for (int jj = 0; jj < 4; jj++) s[i][jj] = 0.f;

#pragma unroll 8
        for (int k = 0; k < 64; k++) {
            float a0 = Qs[(r0 + 0) * 65 + k];
            float a1 = Qs[(r0 + 1) * 65 + k];
            float a2 = Qs[(r0 + 2) * 65 + k];
            float a3 = Qs[(r0 + 3) * 65 + k];
            float b0 = KPs[(c0 + 0) * 65 + k];
            float b1 = KPs[(c0 + 1) * 65 + k];
            float b2 = KPs[(c0 + 2) * 65 + k];
            float b3 = KPs[(c0 + 3) * 65 + k];
            s[0][0] = fmaf(a0, b0, s[0][0]); s[0][1] = fmaf(a0, b1, s[0][1]);
            s[0][2] = fmaf(a0, b2, s[0][2]); s[0][3] = fmaf(a0, b3, s[0][3]);
            s[1][0] = fmaf(a1, b0, s[1][0]); s[1][1] = fmaf(a1, b1, s[1][1]);
            s[1][2] = fmaf(a1, b2, s[1][2]); s[1][3] = fmaf(a1, b3, s[1][3]);
            s[2][0] = fmaf(a2, b0, s[2][0]); s[2][1] = fmaf(a2, b1, s[2][1]);
            s[2][2] = fmaf(a2, b2, s[2][2]); s[2][3] = fmaf(a2, b3, s[2][3]);
            s[3][0] = fmaf(a3, b0, s[3][0]); s[3][1] = fmaf(a3, b1, s[3][1]);
            s[3][2] = fmaf(a3, b2, s[3][2]); s[3][3] = fmaf(a3, b3, s[3][3]);
        }
        __syncthreads();  // done reading KPs as K; safe to overwrite with P

        if (j == qi) {  // diagonal tile: causal mask (qbase == kb here)
#pragma unroll
            for (int i = 0; i < 4; i++)
#pragma unroll
                for (int jj = 0; jj < 4; jj++)
                    if (c0 + jj > r0 + i) s[i][jj] = -1e30f;
        }

        // Online softmax update (row groups = 16 contiguous lanes)
#pragma unroll
        for (int i = 0; i < 4; i++) {
            float mt = fmaxf(fmaxf(s[i][0], s[i][1]), fmaxf(s[i][2], s[i][3]));
#pragma unroll
            for (int off = 8; off >= 1; off >>= 1)
                mt = fmaxf(mt, __shfl_xor_sync(0xffffffffu, mt, off));
            const float mn = fmaxf(mrow[i], mt);
            const float alpha = __expf(mrow[i] - mn);
            mrow[i] = mn;
            float ps = 0.f;
#pragma unroll
            for (int jj = 0; jj < 4; jj++) {
                const float p = __expf(s[i][jj] - mn);
                s[i][jj] = p;
                ps += p;
            }
#pragma unroll
            for (int off = 8; off >= 1; off >>= 1)
                ps += __shfl_xor_sync(0xffffffffu, ps, off);
            lrow[i] = lrow[i] * alpha + ps;
#pragma unroll
            for (int jj = 0; jj < 4; jj++) {
                o[i][jj] *= alpha;
                KPs[(r0 + i) * 65 + c0 + jj] = s[i][jj];  // publish P
            }
        }
        __syncthreads();

        // O += P * V
#pragma unroll 4
        for (int c = 0; c < 64; c++) {
            const float4 vv = *(const float4*)&Vs[c * 64 + c0];
#pragma unroll
            for (int i = 0; i < 4; i++) {
                const float pa = KPs[(r0 + i) * 65 + c];
                o[i][0] = fmaf(pa, vv.x, o[i][0]);
                o[i][1] = fmaf(pa, vv.y, o[i][1]);
                o[i][2] = fmaf(pa, vv.z, o[i][2]);
                o[i][3] = fmaf(pa, vv.w, o[i][3]);
            }
        }
    }

    // Normalize and store in (B,T,C) layout: col = h*64 + d
#pragma unroll
    for (int i = 0; i < 4; i++) {
        const float inv = 1.f / lrow[i];
        float4 cv = { o[i][0] * inv, o[i][1] * inv, o[i][2] * inv, o[i][3] * inv };
        *(float4*)&outp[(brow + qbase + r0 + i) * C_DIM + h * 64 + c0] = cv;
    }
}

// ---------------------------------------------------------------------------
extern "C" void kernel_launch(void* const* d_in, const int* in_sizes, int n_in,
                              void* d_out, int out_size)
{
    const float* x      = (const float*)d_in[0];
    const float* qkv_w  = (const float*)d_in[1];
    const float* qkv_b  = (const float*)d_in[2];
    const float* out_w  = (const float*)d_in[3];
    const float* out_b  = (const float*)d_in[4];
    float* out = (float*)d_out;

    float *qkv_buf = nullptr, *att_buf = nullptr;
    cudaGetSymbolAddress((void**)&qkv_buf, g_qkv);
    cudaGetSymbolAddress((void**)&att_buf, g_att);

    cudaFuncSetAttribute(attn_k, cudaFuncAttributeMaxDynamicSharedMemorySize,
                         SMEM_ATT);

    // 1) QKV projection: (4096 x 1024) @ (1024 x 3072) + bias
    dim3 g1(C3 / 128, MTOT / 128);
    sgemm_bias_k<<<g1, 256>>>(x, qkv_w, qkv_b, qkv_buf, C3, C_DIM);

    // 2) Causal MHA
    dim3 g2(TT / 64, BB * HH);
    attn_k<<<g2, 256, SMEM_ATT>>>(qkv_buf, att_buf);

    // 3) Output projection: (4096 x 1024) @ (1024 x 1024) + bias
    dim3 g3(C_DIM / 128, MTOT / 128);
    sgemm_bias_k<<<g3, 256>>>(att_buf, out_w, out_b, out, C_DIM, C_DIM);
}

// round 2
// speedup vs baseline: 1.0301x; 1.0301x over previous
#include <cuda_runtime.h>

#define C_DIM 1024
#define C3    3072
#define BB    2
#define TT    2048
#define HH    16
#define MTOT  4096   // BB*TT

// Scratch (static device allocations are the sanctioned workaround)
__device__ float g_qkv[(size_t)MTOT * C3];    // QKV activations, row = (b*T+t), col layout [Q|K|V]
__device__ float g_att[(size_t)MTOT * C_DIM]; // attention output in (B,T,C) layout

// ---------------------------------------------------------------------------
// SGEMM v2: C[M][N] = A[M][K] @ B[K][N] + bias[N]. 128x128 tile, BK=8,
// 256 thr, 8x8 micro-tiles, DOUBLE-BUFFERED smem + register prefetch:
// exactly one __syncthreads per k-iteration; LDG latency hidden behind the
// 512-FMA compute phase. launch_bounds(256,2) caps regs at 128 -> 2 CTAs/SM.
// ---------------------------------------------------------------------------
__global__ __launch_bounds__(256, 2) void sgemm_bias_k(
    const float* __restrict__ A, const float* __restrict__ Bm,
    const float* __restrict__ bias, float* __restrict__ Cc,
    int N, int K)
{
    __shared__ float As[2][8][132];   // pad 132: conflict-free transpose stores
    __shared__ float Bs[2][8][132];

    const int t  = threadIdx.x;
    const int tx = t & 15, ty = t >> 4;
    const int m0 = blockIdx.y << 7, n0 = blockIdx.x << 7;

    const int arow = t >> 1, apart = (t & 1) << 2;   // A: 128 rows x 8 cols
    const int brow = t >> 5, bcol = (t & 31) << 2;   // B: 8 rows x 128 cols

    const float* Aptr = A  + (size_t)(m0 + arow) * K + apart;
    const float* Bptr = Bm + (size_t)brow * N + n0 + bcol;

    float acc[8][8];
#pragma unroll
    for (int i = 0; i < 8; i++)
#pragma unroll
        for (int j = 0; j < 8; j++) acc[i][j] = 0.f;

    // Preload tile 0 into buffer 0
    {
        float4 av = *(const float4*)(Aptr);
        float4 bv = *(const float4*)(Bptr);
        As[0][apart + 0][arow] = av.x;
        As[0][apart + 1][arow] = av.y;
        As[0][apart + 2][arow] = av.z;
        As[0][apart + 3][arow] = av.w;
        *(float4*)&Bs[0][brow][bcol] = bv;
    }
    __syncthreads();

    int buf = 0;
    for (int k0 = 8; k0 < K; k0 += 8) {
        // Prefetch next tile into registers (LDG issued before compute phase)
        float4 av = *(const float4*)(Aptr + k0);
        float4 bv = *(const float4*)(Bptr + (size_t)k0 * N);

        // Compute on current buffer
#pragma unroll
        for (int kk = 0; kk < 8; kk++) {
            float a[8], b[8];
            *(float4*)(a)     = *(const float4*)&As[buf][kk][ty * 8];
            *(float4*)(a + 4) = *(const float4*)&As[buf][kk][ty * 8 + 4];
            *(float4*)(b)     = *(const float4*)&Bs[buf][kk][tx * 8];
            *(float4*)(b + 4) = *(const float4*)&Bs[buf][kk][tx * 8 + 4];
#pragma unroll
            for (int i = 0; i < 8; i++)
#pragma unroll
                for (int j = 0; j < 8; j++)
                    acc[i][j] = fmaf(a[i], b[j], acc[i][j]);
        }

        // Stage prefetched tile into the other buffer
        const int nb = buf ^ 1;
        As[nb][apart + 0][arow] = av.x;
        As[nb][apart + 1][arow] = av.y;
        As[nb][apart + 2][arow] = av.z;
        As[nb][apart + 3][arow] = av.w;
        *(float4*)&Bs[nb][brow][bcol] = bv;
        __syncthreads();
        buf = nb;
    }

    // Final tile
#pragma unroll
    for (int kk = 0; kk < 8; kk++) {
        float a[8], b[8];
        *(float4*)(a)     = *(const float4*)&As[buf][kk][ty * 8];
        *(float4*)(a + 4) = *(const float4*)&As[buf][kk][ty * 8 + 4];
        *(float4*)(b)     = *(const float4*)&Bs[buf][kk][tx * 8];
        *(float4*)(b + 4) = *(const float4*)&Bs[buf][kk][tx * 8 + 4];
#pragma unroll
        for (int i = 0; i < 8; i++)
#pragma unroll
            for (int j = 0; j < 8; j++)
                acc[i][j] = fmaf(a[i], b[j], acc[i][j]);
    }

#pragma unroll
    for (int i = 0; i < 8; i++) {
        const int m = m0 + ty * 8 + i;
#pragma unroll
        for (int hlf = 0; hlf < 2; hlf++) {
            const int n = n0 + tx * 8 + hlf * 4;
            float4 bv = *(const float4*)&bias[n];
            float4 cv;
            cv.x = acc[i][hlf * 4 + 0] + bv.x;
            cv.y = acc[i][hlf * 4 + 1] + bv.y;
            cv.z = acc[i][hlf * 4 + 2] + bv.z;
            cv.w = acc[i][hlf * 4 + 3] + bv.w;
            *(float4*)&Cc[(size_t)m * N + n] = cv;
        }
    }
}

// ---------------------------------------------------------------------------
// Causal flash attention, fp32. One block = one (b,h) and a 64-query tile.
// 256 threads; each thread owns a 4x4 S/P micro-tile and a 4x4 O micro-tile.
// Online softmax; K-tile and P-tile share one smem buffer (phase-separated).
// Dynamic smem = Qs[64][65] + KP[64][65] + Vs[64][64] = 49664 B.
// ---------------------------------------------------------------------------
#define SMEM_ATT ((64 * 65 * 2 + 64 * 64) * 4)

__global__ __launch_bounds__(256) void attn_k(const float* __restrict__ qkv,
                                              float* __restrict__ outp)
{
    extern __shared__ float sm[];
    float* Qs  = sm;               // [64][65], pre-scaled by 1/sqrt(Dh)
    float* KPs = sm + 64 * 65;     // [64][65], K-tile then P-tile
    float* Vs  = sm + 2 * 64 * 65; // [64][64]

    const int t  = threadIdx.x;
    const int qi = gridDim.x - 1 - blockIdx.x;  // heavy tiles first (wave packing)
    const int bh = blockIdx.y;
    const int b  = bh >> 4, h = bh & 15;
    const int r0 = (t >> 4) << 2;   // 4 query rows
    const int c0 = (t & 15) << 2;   // 4 key cols / 4 out dims
    const int qbase = qi << 6;
    const size_t brow = (size_t)b * TT;

    // Load + pre-scale Q tile (float4 gmem loads)
    for (int idx = t; idx < 1024; idx += 256) {
        const int r = idx >> 4, k4 = (idx & 15) << 2;
        float4 v = *(const float4*)&qkv[(brow + qbase + r) * C3 + h * 64 + k4];
        Qs[r * 65 + k4 + 0] = v.x * 0.125f;
        Qs[r * 65 + k4 + 1] = v.y * 0.125f;
        Qs[r * 65 + k4 + 2] = v.z * 0.125f;
        Qs[r * 65 + k4 + 3] = v.w * 0.125f;
    }

    float o[4][4];
    float mrow[4], lrow[4];
#pragma unroll
    for (int i = 0; i < 4; i++) {
        mrow[i] = -1e30f; lrow[i] = 0.f;
#pragma unroll
        for (int j = 0; j < 4; j++) o[i][j] = 0.f;
    }

    for (int j = 0; j <= qi; j++) {
        __syncthreads();  // prev PV reads done (also covers Q fill on iter 0)
        const int kb = j << 6;
        for (int idx = t; idx < 1024; idx += 256) {
            const int r = idx >> 4, k4 = (idx & 15) << 2;
            const size_t g = (brow + kb + r) * C3 + h * 64 + k4;
            float4 kv = *(const float4*)&qkv[g + 1024];
            float4 vv = *(const float4*)&qkv[g + 2048];
            KPs[r * 65 + k4 + 0] = kv.x;
            KPs[r * 65 + k4 + 1] = kv.y;
            KPs[r * 65 + k4 + 2] = kv.z;
            KPs[r * 65 + k4 + 3] = kv.w;
            *(float4*)&Vs[r * 64 + k4] = vv;
        }
        __syncthreads();

        // S = Q * K^T   (4x4 micro-tile per thread)
        float s[4][4];
#pragma unroll
        for (int i = 0; i < 4; i++)
#pragma unroll
            for (int jj = 0; jj < 4; jj++) s[i][jj] = 0.f;

#pragma unroll 8
        for (int k = 0; k < 64; k++) {
            float a0 = Qs[(r0 + 0) * 65 + k];
            float a1 = Qs[(r0 + 1) * 65 + k];
            float a2 = Qs[(r0 + 2) * 65 + k];
            float a3 = Qs[(r0 + 3) * 65 + k];
            float b0 = KPs[(c0 + 0) * 65 + k];
            float b1 = KPs[(c0 + 1) * 65 + k];
            float b2 = KPs[(c0 + 2) * 65 + k];
            float b3 = KPs[(c0 + 3) * 65 + k];
            s[0][0] = fmaf(a0, b0, s[0][0]); s[0][1] = fmaf(a0, b1, s[0][1]);
            s[0][2] = fmaf(a0, b2, s[0][2]); s[0][3] = fmaf(a0, b3, s[0][3]);
            s[1][0] = fmaf(a1, b0, s[1][0]); s[1][1] = fmaf(a1, b1, s[1][1]);
            s[1][2] = fmaf(a1, b2, s[1][2]); s[1][3] = fmaf(a1, b3, s[1][3]);
            s[2][0] = fmaf(a2, b0, s[2][0]); s[2][1] = fmaf(a2, b1, s[2][1]);
            s[2][2] = fmaf(a2, b2, s[2][2]); s[2][3] = fmaf(a2, b3, s[2][3]);
            s[3][0] = fmaf(a3, b0, s[3][0]); s[3][1] = fmaf(a3, b1, s[3][1]);
            s[3][2] = fmaf(a3, b2, s[3][2]); s[3][3] = fmaf(a3, b3, s[3][3]);
        }
        __syncthreads();  // done reading KPs as K; safe to overwrite with P

        if (j == qi) {  // diagonal tile: causal mask (qbase == kb here)
#pragma unroll
            for (int i = 0; i < 4; i++)
#pragma unroll
                for (int jj = 0; jj < 4; jj++)
                    if (c0 + jj > r0 + i) s[i][jj] = -1e30f;
        }

        // Online softmax update (row groups = 16 contiguous lanes)
#pragma unroll
        for (int i = 0; i < 4; i++) {
            float mt = fmaxf(fmaxf(s[i][0], s[i][1]), fmaxf(s[i][2], s[i][3]));
#pragma unroll
            for (int off = 8; off >= 1; off >>= 1)
                mt = fmaxf(mt, __shfl_xor_sync(0xffffffffu, mt, off));
            const float mn = fmaxf(mrow[i], mt);
            const float alpha = __expf(mrow[i] - mn);
            mrow[i] = mn;
            float ps = 0.f;
#pragma unroll
            for (int jj = 0; jj < 4; jj++) {
                const float p = __expf(s[i][jj] - mn);
                s[i][jj] = p;
                ps += p;
            }
#pragma unroll
            for (int off = 8; off >= 1; off >>= 1)
                ps += __shfl_xor_sync(0xffffffffu, ps, off);
            lrow[i] = lrow[i] * alpha + ps;
#pragma unroll
            for (int jj = 0; jj < 4; jj++) {
                o[i][jj] *= alpha;
                KPs[(r0 + i) * 65 + c0 + jj] = s[i][jj];  // publish P
            }
        }
        __syncthreads();

        // O += P * V
#pragma unroll 4
        for (int c = 0; c < 64; c++) {
            const float4 vv = *(const float4*)&Vs[c * 64 + c0];
#pragma unroll
            for (int i = 0; i < 4; i++) {
                const float pa = KPs[(r0 + i) * 65 + c];
                o[i][0] = fmaf(pa, vv.x, o[i][0]);
                o[i][1] = fmaf(pa, vv.y, o[i][1]);
                o[i][2] = fmaf(pa, vv.z, o[i][2]);
                o[i][3] = fmaf(pa, vv.w, o[i][3]);
            }
        }
    }

    // Normalize and store in (B,T,C) layout: col = h*64 + d
#pragma unroll
    for (int i = 0; i < 4; i++) {
        const float inv = 1.f / lrow[i];
        float4 cv = { o[i][0] * inv, o[i][1] * inv, o[i][2] * inv, o[i][3] * inv };
        *(float4*)&outp[(brow + qbase + r0 + i) * C_DIM + h * 64 + c0] = cv;
    }
}

// ---------------------------------------------------------------------------
extern "C" void kernel_launch(void* const* d_in, const int* in_sizes, int n_in,
                              void* d_out, int out_size)
{
    const float* x      = (const float*)d_in[0];
    const float* qkv_w  = (const float*)d_in[1];
    const float* qkv_b  = (const float*)d_in[2];
    const float* out_w  = (const float*)d_in[3];
    const float* out_b  = (const float*)d_in[4];
    float* out = (float*)d_out;

    float *qkv_buf = nullptr, *att_buf = nullptr;
    cudaGetSymbolAddress((void**)&qkv_buf, g_qkv);
    cudaGetSymbolAddress((void**)&att_buf, g_att);

    cudaFuncSetAttribute(attn_k, cudaFuncAttributeMaxDynamicSharedMemorySize,
                         SMEM_ATT);

    // 1) QKV projection: (4096 x 1024) @ (1024 x 3072) + bias
    dim3 g1(C3 / 128, MTOT / 128);
    sgemm_bias_k<<<g1, 256>>>(x, qkv_w, qkv_b, qkv_buf, C3, C_DIM);

    // 2) Causal MHA
    dim3 g2(TT / 64, BB * HH);
    attn_k<<<g2, 256, SMEM_ATT>>>(qkv_buf, att_buf);

    // 3) Output projection: (4096 x 1024) @ (1024 x 1024) + bias
    dim3 g3(C_DIM / 128, MTOT / 128);
    sgemm_bias_k<<<g3, 256>>>(att_buf, out_w, out_b, out, C_DIM, C_DIM);
}

// round 4
// speedup vs baseline: 1.5838x; 1.5376x over previous
#include <cuda_runtime.h>
#include <cuda_bf16.h>
#include <cstdint>

#define C_DIM 1024
#define C3    3072
#define BB    2
#define TT    2048
#define HH    16
#define MTOT  4096   // BB*TT

// ---------------------------------------------------------------------------
// Scratch buffers (__device__ globals: the sanctioned no-alloc workaround)
// ---------------------------------------------------------------------------
__device__ float g_qkv[(size_t)MTOT * C3];      // QKV activations [row][Q|K|V]
__device__ float g_att[(size_t)MTOT * C_DIM];   // attention output (B,T,C)
__device__ __nv_bfloat16 g_xhi[(size_t)MTOT * C_DIM];
__device__ __nv_bfloat16 g_xlo[(size_t)MTOT * C_DIM];
__device__ __nv_bfloat16 g_ahi[(size_t)MTOT * C_DIM];
__device__ __nv_bfloat16 g_alo[(size_t)MTOT * C_DIM];
__device__ __nv_bfloat16 g_wqt_hi[(size_t)C3 * C_DIM];   // qkv_w^T [N=3072][K=1024]
__device__ __nv_bfloat16 g_wqt_lo[(size_t)C3 * C_DIM];
__device__ __nv_bfloat16 g_wot_hi[(size_t)C_DIM * C_DIM];
__device__ __nv_bfloat16 g_wot_lo[(size_t)C_DIM * C_DIM];

// ---------------------------------------------------------------------------
// Portable tensor-core helpers (compute_103-safe: ldmatrix / mma.sync / cp.async)
// ---------------------------------------------------------------------------
__device__ __forceinline__ uint32_t smem_u32(const void* p) {
    uint32_t a;
    asm("{ .reg .u64 t; cvta.to.shared.u64 t, %1; cvt.u32.u64 %0, t; }"
        : "=r"(a) : "l"(p));
    return a;
}
#define SWZ128(off) ((off) ^ (((off) >> 3) & 0x70))

__device__ __forceinline__ void ldsm4(uint32_t* r, uint32_t addr) {
    asm volatile("ldmatrix.sync.aligned.m8n8.x4.shared.b16 {%0,%1,%2,%3}, [%4];"
        : "=r"(r[0]), "=r"(r[1]), "=r"(r[2]), "=r"(r[3]) : "r"(addr));
}
__device__ __forceinline__ void mma_bf16(float* d, const uint32_t* a, const uint32_t* b) {
    asm volatile("mma.sync.aligned.m16n8k16.row.col.f32.bf16.bf16.f32 "
        "{%0,%1,%2,%3}, {%4,%5,%6,%7}, {%8,%9}, {%0,%1,%2,%3};"
        : "+f"(d[0]), "+f"(d[1]), "+f"(d[2]), "+f"(d[3])
        : "r"(a[0]), "r"(a[1]), "r"(a[2]), "r"(a[3]), "r"(b[0]), "r"(b[1]));
}
#define CP16(dst, src)  asm volatile("cp.async.cg.shared.global [%0], [%1], 16;" :: "r"(dst), "l"(src) : "memory")
#define CP_COMMIT()     asm volatile("cp.async.commit_group;" ::: "memory")
#define CP_WAIT0()      asm volatile("cp.async.wait_group 0;" ::: "memory")

// ---------------------------------------------------------------------------
// Prepass: fp32 -> (hi, lo) bf16 split.  n4 = element_count/4.
// ---------------------------------------------------------------------------
__global__ __launch_bounds__(256) void split_k(const float* __restrict__ in,
    __nv_bfloat16* __restrict__ hi, __nv_bfloat16* __restrict__ lo, int n4)
{
    const int i = blockIdx.x * 256 + threadIdx.x;
    if (i >= n4) return;
    const float4 v = ((const float4*)in)[i];
    __nv_bfloat16 h0 = __float2bfloat16(v.x), h1 = __float2bfloat16(v.y);
    __nv_bfloat16 h2 = __float2bfloat16(v.z), h3 = __float2bfloat16(v.w);
    __nv_bfloat162 hp0, hp1, lp0, lp1;
    hp0.x = h0; hp0.y = h1; hp1.x = h2; hp1.y = h3;
    lp0.x = __float2bfloat16(v.x - __bfloat162float(h0));
    lp0.y = __float2bfloat16(v.y - __bfloat162float(h1));
    lp1.x = __float2bfloat16(v.z - __bfloat162float(h2));
    lp1.y = __float2bfloat16(v.w - __bfloat162float(h3));
    ((__nv_bfloat162*)hi)[i * 2 + 0] = hp0;
    ((__nv_bfloat162*)hi)[i * 2 + 1] = hp1;
    ((__nv_bfloat162*)lo)[i * 2 + 0] = lp0;
    ((__nv_bfloat162*)lo)[i * 2 + 1] = lp1;
}

// ---------------------------------------------------------------------------
// Prepass: transpose + split.  in [K][N] fp32 -> out hi/lo [N][K] bf16.
// ---------------------------------------------------------------------------
__global__ __launch_bounds__(256) void tsplit_k(const float* __restrict__ in,
    __nv_bfloat16* __restrict__ hiT, __nv_bfloat16* __restrict__ loT, int K, int N)
{
    __shared__ float tile[32][33];
    const int n0 = blockIdx.x * 32, k0 = blockIdx.y * 32;
    const int tx = threadIdx.x, ty = threadIdx.y;
    for (int i = ty; i < 32; i += 8)
        tile[i][tx] = in[(size_t)(k0 + i) * N + n0 + tx];
    __syncthreads();
    for (int i = ty; i < 32; i += 8) {
        const float v = tile[tx][i];
        const __nv_bfloat16 h = __float2bfloat16(v);
        hiT[(size_t)(n0 + i) * K + k0 + tx] = h;
        loT[(size_t)(n0 + i) * K + k0 + tx] = __float2bfloat16(v - __bfloat162float(h));
    }
}

// ---------------------------------------------------------------------------
// mma.sync GEMM: C[128x128 per CTA] = A @ B^T + bias, fp32 out.
// A as (Ahi,Alo) K-major [M][1024]; B as (Bhi,Blo) K-major [N][1024].
// Split precision: D += AhBh + AhBl + AlBh (fp32 accum in HMMA).
// BK=64 chunks, cp.async double buffer (2 x 64KB), SW128 swizzle, ldmatrix.
// 8 warps: 4(M) x 2(N); warp tile 32x64 -> acc[2][8][4].
// ---------------------------------------------------------------------------
#define GTILE_B   16384                   // one 128x64 bf16 tile
#define GBUF_B    (4 * GTILE_B)           // Ah Al Bh Bl
#define SMEM_GEMM (2 * GBUF_B)            // 131072

__global__ __launch_bounds__(256) void gemm_mma(
    const __nv_bfloat16* __restrict__ Ahi, const __nv_bfloat16* __restrict__ Alo,
    const __nv_bfloat16* __restrict__ Bhi, const __nv_bfloat16* __restrict__ Blo,
    const float* __restrict__ bias, float* __restrict__ Cc, int Ntot)
{
    extern __shared__ __align__(1024) char smg[];
    const uint32_t sb = smem_u32(smg);
    const int t = threadIdx.x, w = t >> 5, lane = t & 31;
    const int m0 = blockIdx.y << 7, n0 = blockIdx.x << 7;
    const int wm = (w >> 1) << 5, wn = (w & 1) << 6;

    const __nv_bfloat16* srcs[4] = {
        Ahi + (size_t)m0 * 1024, Alo + (size_t)m0 * 1024,
        Bhi + (size_t)n0 * 1024, Blo + (size_t)n0 * 1024 };

    float acc[2][8][4];
#pragma unroll
    for (int i = 0; i < 2; i++)
#pragma unroll
        for (int j = 0; j < 8; j++)
#pragma unroll
            for (int q = 0; q < 4; q++) acc[i][j][q] = 0.f;

    // Fill helper (chunk c -> buffer buf)
    auto fill = [&](int c, int buf) {
        const int k0 = c << 6;
        const uint32_t bufb = sb + buf * GBUF_B;
#pragma unroll
        for (int tile = 0; tile < 4; ++tile) {
            const __nv_bfloat16* s = srcs[tile] + k0;
            const uint32_t db = bufb + tile * GTILE_B;
#pragma unroll
            for (int i = 0; i < 4; ++i) {
                const int idx = t + (i << 8);        // 0..1023
                const int row = idx >> 3, seg = idx & 7;
                CP16(db + SWZ128(row * 128 + seg * 16),
                     s + (size_t)row * 1024 + seg * 8);
            }
        }
    };

    fill(0, 0);
    CP_COMMIT();
    CP_WAIT0();
    __syncthreads();

    const int aRow = wm + (lane & 15);
    const int bRow = wn + ((lane >> 4) << 3) + (lane & 7);

    for (int c = 0; c < 16; ++c) {
        const int buf = c & 1;
        if (c < 15) { fill(c + 1, buf ^ 1); CP_COMMIT(); }

        const uint32_t bA_h = sb + buf * GBUF_B;
        const uint32_t bA_l = bA_h + GTILE_B;
        const uint32_t bB_h = bA_h + 2 * GTILE_B;
        const uint32_t bB_l = bA_h + 3 * GTILE_B;

#pragma unroll
        for (int k16 = 0; k16 < 4; ++k16) {
            const int kbA = k16 * 32 + ((lane >> 4) & 1) * 16;
            const int kbB = k16 * 32 + ((lane >> 3) & 1) * 16;

            uint32_t aH[2][4], aL[2][4];
#pragma unroll
            for (int mi = 0; mi < 2; ++mi) {
                const uint32_t off = SWZ128((aRow + mi * 16) * 128 + kbA);
                ldsm4(aH[mi], bA_h + off);
                ldsm4(aL[mi], bA_l + off);
            }
            uint32_t bH[4][4], bL[4][4];
#pragma unroll
            for (int ni = 0; ni < 4; ++ni) {
                const uint32_t off = SWZ128((bRow + ni * 16) * 128 + kbB);
                ldsm4(bH[ni], bB_h + off);
                ldsm4(bL[ni], bB_l + off);
            }
#pragma unroll
            for (int mi = 0; mi < 2; ++mi)
#pragma unroll
                for (int ni = 0; ni < 4; ++ni)
#pragma unroll
                    for (int h2 = 0; h2 < 2; ++h2) {
                        float* d = acc[mi][ni * 2 + h2];
                        mma_bf16(d, aH[mi], &bH[ni][h2 * 2]);
                        mma_bf16(d, aH[mi], &bL[ni][h2 * 2]);
                        mma_bf16(d, aL[mi], &bH[ni][h2 * 2]);
                    }
        }
        CP_WAIT0();
        __syncthreads();
    }

    // Epilogue: direct fp32 stores + bias (c0/c1 = row g, c2/c3 = row g+8)
    const int g2 = lane >> 2, tg = lane & 3;
#pragma unroll
    for (int mi = 0; mi < 2; ++mi) {
        const int row0 = m0 + wm + mi * 16 + g2;
#pragma unroll
        for (int j = 0; j < 8; ++j) {
            const int col = n0 + wn + j * 8 + tg * 2;
            const float2 b2 = *(const float2*)&bias[col];
            const float* d = acc[mi][j];
            float2 lo2 = { d[0] + b2.x, d[1] + b2.y };
            float2 hi2 = { d[2] + b2.x, d[3] + b2.y };
            *(float2*)&Cc[(size_t)row0 * Ntot + col] = lo2;
            *(float2*)&Cc[(size_t)(row0 + 8) * Ntot + col] = hi2;
        }
    }
}

// ---------------------------------------------------------------------------
// Causal flash attention, fp32 (unchanged from passing R2 kernel).
// ---------------------------------------------------------------------------
#define SMEM_ATT ((64 * 65 * 2 + 64 * 64) * 4)

__global__ __launch_bounds__(256) void attn_k(const float* __restrict__ qkv,
                                              float* __restrict__ outp)
{
    extern __shared__ float smf[];
    float* Qs  = smf;
    float* KPs = smf + 64 * 65;
    float* Vs  = smf + 2 * 64 * 65;

    const int t  = threadIdx.x;
    const int qi = gridDim.x - 1 - blockIdx.x;
    const int bh = blockIdx.y;
    const int b  = bh >> 4, h = bh & 15;
    const int r0 = (t >> 4) << 2;
    const int c0 = (t & 15) << 2;
    const int qbase = qi << 6;
    const size_t brow = (size_t)b * TT;

    for (int idx = t; idx < 1024; idx += 256) {
        const int r = idx >> 4, k4 = (idx & 15) << 2;
        float4 v = *(const float4*)&qkv[(brow + qbase + r) * C3 + h * 64 + k4];
        Qs[r * 65 + k4 + 0] = v.x * 0.125f;
        Qs[r * 65 + k4 + 1] = v.y * 0.125f;
        Qs[r * 65 + k4 + 2] = v.z * 0.125f;
        Qs[r * 65 + k4 + 3] = v.w * 0.125f;
    }

    float o[4][4];
    float mrow[4], lrow[4];
#pragma unroll
    for (int i = 0; i < 4; i++) {
        mrow[i] = -1e30f; lrow[i] = 0.f;
#pragma unroll
        for (int j = 0; j < 4; j++) o[i][j] = 0.f;
    }

    for (int j = 0; j <= qi; j++) {
        __syncthreads();
        const int kb = j << 6;
        for (int idx = t; idx < 1024; idx += 256) {
            const int r = idx >> 4, k4 = (idx & 15) << 2;
            const size_t g = (brow + kb + r) * C3 + h * 64 + k4;
            float4 kv = *(const float4*)&qkv[g + 1024];
            float4 vv = *(const float4*)&qkv[g + 2048];
            KPs[r * 65 + k4 + 0] = kv.x;
            KPs[r * 65 + k4 + 1] = kv.y;
            KPs[r * 65 + k4 + 2] = kv.z;
            KPs[r * 65 + k4 + 3] = kv.w;
            *(float4*)&Vs[r * 64 + k4] = vv;
        }
        __syncthreads();

        float s[4][4];
#pragma unroll
        for (int i = 0; i < 4; i++)
#pragma unroll
            for (int jj = 0; jj < 4; jj++) s[i][jj] = 0.f;

#pragma unroll 8
        for (int k = 0; k < 64; k++) {
            float a0 = Qs[(r0 + 0) * 65 + k];
            float a1 = Qs[(r0 + 1) * 65 + k];
            float a2 = Qs[(r0 + 2) * 65 + k];
            float a3 = Qs[(r0 + 3) * 65 + k];
            float b0 = KPs[(c0 + 0) * 65 + k];
            float b1 = KPs[(c0 + 1) * 65 + k];
            float b2 = KPs[(c0 + 2) * 65 + k];
            float b3 = KPs[(c0 + 3) * 65 + k];
            s[0][0] = fmaf(a0, b0, s[0][0]); s[0][1] = fmaf(a0, b1, s[0][1]);
            s[0][2] = fmaf(a0, b2, s[0][2]); s[0][3] = fmaf(a0, b3, s[0][3]);
            s[1][0] = fmaf(a1, b0, s[1][0]); s[1][1] = fmaf(a1, b1, s[1][1]);
            s[1][2] = fmaf(a1, b2, s[1][2]); s[1][3] = fmaf(a1, b3, s[1][3]);
            s[2][0] = fmaf(a2, b0, s[2][0]); s[2][1] = fmaf(a2, b1, s[2][1]);
            s[2][2] = fmaf(a2, b2, s[2][2]); s[2][3] = fmaf(a2, b3, s[2][3]);
            s[3][0] = fmaf(a3, b0, s[3][0]); s[3][1] = fmaf(a3, b1, s[3][1]);
            s[3][2] = fmaf(a3, b2, s[3][2]); s[3][3] = fmaf(a3, b3, s[3][3]);
        }
        __syncthreads();

        if (j == qi) {
#pragma unroll
            for (int i = 0; i < 4; i++)
#pragma unroll
                for (int jj = 0; jj < 4; jj++)
                    if (c0 + jj > r0 + i) s[i][jj] = -1e30f;
        }

#pragma unroll
        for (int i = 0; i < 4; i++) {
            float mt = fmaxf(fmaxf(s[i][0], s[i][1]), fmaxf(s[i][2], s[i][3]));
#pragma unroll
            for (int off = 8; off >= 1; off >>= 1)
                mt = fmaxf(mt, __shfl_xor_sync(0xffffffffu, mt, off));
            const float mn = fmaxf(mrow[i], mt);
            const float alpha = __expf(mrow[i] - mn);
            mrow[i] = mn;
            float ps = 0.f;
#pragma unroll
            for (int jj = 0; jj < 4; jj++) {
                const float p = __expf(s[i][jj] - mn);
                s[i][jj] = p;
                ps += p;
            }
#pragma unroll
            for (int off = 8; off >= 1; off >>= 1)
                ps += __shfl_xor_sync(0xffffffffu, ps, off);
            lrow[i] = lrow[i] * alpha + ps;
#pragma unroll
            for (int jj = 0; jj < 4; jj++) {
                o[i][jj] *= alpha;
                KPs[(r0 + i) * 65 + c0 + jj] = s[i][jj];
            }
        }
        __syncthreads();

#pragma unroll 4
        for (int c = 0; c < 64; c++) {
            const float4 vv = *(const float4*)&Vs[c * 64 + c0];
#pragma unroll
            for (int i = 0; i < 4; i++) {
                const float pa = KPs[(r0 + i) * 65 + c];
                o[i][0] = fmaf(pa, vv.x, o[i][0]);
                o[i][1] = fmaf(pa, vv.y, o[i][1]);
                o[i][2] = fmaf(pa, vv.z, o[i][2]);
                o[i][3] = fmaf(pa, vv.w, o[i][3]);
            }
        }
    }

#pragma unroll
    for (int i = 0; i < 4; i++) {
        const float inv = 1.f / lrow[i];
        float4 cv = { o[i][0] * inv, o[i][1] * inv, o[i][2] * inv, o[i][3] * inv };
        *(float4*)&outp[(brow + qbase + r0 + i) * C_DIM + h * 64 + c0] = cv;
    }
}

// ---------------------------------------------------------------------------
extern "C" void kernel_launch(void* const* d_in, const int* in_sizes, int n_in,
                              void* d_out, int out_size)
{
    const float* x      = (const float*)d_in[0];
    const float* qkv_w  = (const float*)d_in[1];
    const float* qkv_b  = (const float*)d_in[2];
    const float* out_w  = (const float*)d_in[3];
    const float* out_b  = (const float*)d_in[4];
    float* out = (float*)d_out;

    float *qkv_buf, *att_buf;
    __nv_bfloat16 *xhi, *xlo, *ahi, *alo, *wqh, *wql, *woh, *wol;
    cudaGetSymbolAddress((void**)&qkv_buf, g_qkv);
    cudaGetSymbolAddress((void**)&att_buf, g_att);
    cudaGetSymbolAddress((void**)&xhi, g_xhi);
    cudaGetSymbolAddress((void**)&xlo, g_xlo);
    cudaGetSymbolAddress((void**)&ahi, g_ahi);
    cudaGetSymbolAddress((void**)&alo, g_alo);
    cudaGetSymbolAddress((void**)&wqh, g_wqt_hi);
    cudaGetSymbolAddress((void**)&wql, g_wqt_lo);
    cudaGetSymbolAddress((void**)&woh, g_wot_hi);
    cudaGetSymbolAddress((void**)&wol, g_wot_lo);

    cudaFuncSetAttribute(attn_k, cudaFuncAttributeMaxDynamicSharedMemorySize, SMEM_ATT);
    cudaFuncSetAttribute(gemm_mma, cudaFuncAttributeMaxDynamicSharedMemorySize, SMEM_GEMM);

    // Prepasses: split x; transpose+split weights
    split_k<<<(MTOT * C_DIM / 4 + 255) / 256, 256>>>(x, xhi, xlo, MTOT * C_DIM / 4);
    tsplit_k<<<dim3(C3 / 32, C_DIM / 32), dim3(32, 8)>>>(qkv_w, wqh, wql, C_DIM, C3);
    tsplit_k<<<dim3(C_DIM / 32, C_DIM / 32), dim3(32, 8)>>>(out_w, woh, wol, C_DIM, C_DIM);

    // 1) QKV projection (mma.sync bf16 split): (4096 x 1024) @ (1024 x 3072) + bias
    gemm_mma<<<dim3(C3 / 128, MTOT / 128), 256, SMEM_GEMM>>>(
        xhi, xlo, wqh, wql, qkv_b, qkv_buf, C3);

    // 2) Causal MHA (fp32 SIMT)
    attn_k<<<dim3(TT / 64, BB * HH), 256, SMEM_ATT>>>(qkv_buf, att_buf);

    // 3) Split attention output, then output projection (mma.sync)
    split_k<<<(MTOT * C_DIM / 4 + 255) / 256, 256>>>(att_buf, ahi, alo, MTOT * C_DIM / 4);
    gemm_mma<<<dim3(C_DIM / 128, MTOT / 128), 256, SMEM_GEMM>>>(
        ahi, alo, woh, wol, out_b, out, C_DIM);
}

// round 5
// speedup vs baseline: 2.3494x; 1.4834x over previous
#include <cuda_runtime.h>
#include <cuda_bf16.h>
#include <cstdint>

#define C_DIM 1024
#define C3    3072
#define BB    2
#define TT    2048
#define HH    16
#define MTOT  4096   // BB*TT

// ---------------------------------------------------------------------------
// Scratch buffers (__device__ globals: the sanctioned no-alloc workaround)
// ---------------------------------------------------------------------------
__device__ float g_qkv[(size_t)MTOT * C3];      // QKV activations [row][Q|K|V]
__device__ __nv_bfloat16 g_xhi[(size_t)MTOT * C_DIM];
__device__ __nv_bfloat16 g_xlo[(size_t)MTOT * C_DIM];
__device__ __nv_bfloat16 g_ahi[(size_t)MTOT * C_DIM];   // attn out hi (K-major)
__device__ __nv_bfloat16 g_alo[(size_t)MTOT * C_DIM];   // attn out lo
__device__ __nv_bfloat16 g_wqt_hi[(size_t)C3 * C_DIM];  // qkv_w^T [N=3072][K=1024]
__device__ __nv_bfloat16 g_wqt_lo[(size_t)C3 * C_DIM];
__device__ __nv_bfloat16 g_wot_hi[(size_t)C_DIM * C_DIM];
__device__ __nv_bfloat16 g_wot_lo[(size_t)C_DIM * C_DIM];

// ---------------------------------------------------------------------------
// Portable tensor-core helpers (compute_103-safe: ldmatrix / mma.sync / cp.async)
// ---------------------------------------------------------------------------
__device__ __forceinline__ uint32_t smem_u32(const void* p) {
    uint32_t a;
    asm("{ .reg .u64 t; cvta.to.shared.u64 t, %1; cvt.u32.u64 %0, t; }"
        : "=r"(a) : "l"(p));
    return a;
}
#define SWZ128(off) ((off) ^ (((off) >> 3) & 0x70))

__device__ __forceinline__ void ldsm4(uint32_t* r, uint32_t addr) {
    asm volatile("ldmatrix.sync.aligned.m8n8.x4.shared.b16 {%0,%1,%2,%3}, [%4];"
        : "=r"(r[0]), "=r"(r[1]), "=r"(r[2]), "=r"(r[3]) : "r"(addr));
}
__device__ __forceinline__ void mma_bf16(float* d, const uint32_t* a, const uint32_t* b) {
    asm volatile("mma.sync.aligned.m16n8k16.row.col.f32.bf16.bf16.f32 "
        "{%0,%1,%2,%3}, {%4,%5,%6,%7}, {%8,%9}, {%0,%1,%2,%3};"
        : "+f"(d[0]), "+f"(d[1]), "+f"(d[2]), "+f"(d[3])
        : "r"(a[0]), "r"(a[1]), "r"(a[2]), "r"(a[3]), "r"(b[0]), "r"(b[1]));
}
#define CP16(dst, src)  asm volatile("cp.async.cg.shared.global [%0], [%1], 16;" :: "r"(dst), "l"(src) : "memory")
#define CP_COMMIT()     asm volatile("cp.async.commit_group;" ::: "memory")
#define CP_WAIT0()      asm volatile("cp.async.wait_group 0;" ::: "memory")

__device__ __forceinline__ uint32_t pack_bf16(float a, float b) {
    __nv_bfloat162 p;
    p.x = __float2bfloat16(a);
    p.y = __float2bfloat16(b);
    return *(uint32_t*)&p;
}

// ---------------------------------------------------------------------------
// Prepass: fp32 -> (hi, lo) bf16 split.  n4 = element_count/4.
// ---------------------------------------------------------------------------
__global__ __launch_bounds__(256) void split_k(const float* __restrict__ in,
    __nv_bfloat16* __restrict__ hi, __nv_bfloat16* __restrict__ lo, int n4)
{
    const int i = blockIdx.x * 256 + threadIdx.x;
    if (i >= n4) return;
    const float4 v = ((const float4*)in)[i];
    __nv_bfloat16 h0 = __float2bfloat16(v.x), h1 = __float2bfloat16(v.y);
    __nv_bfloat16 h2 = __float2bfloat16(v.z), h3 = __float2bfloat16(v.w);
    __nv_bfloat162 hp0, hp1, lp0, lp1;
    hp0.x = h0; hp0.y = h1; hp1.x = h2; hp1.y = h3;
    lp0.x = __float2bfloat16(v.x - __bfloat162float(h0));
    lp0.y = __float2bfloat16(v.y - __bfloat162float(h1));
    lp1.x = __float2bfloat16(v.z - __bfloat162float(h2));
    lp1.y = __float2bfloat16(v.w - __bfloat162float(h3));
    ((__nv_bfloat162*)hi)[i * 2 + 0] = hp0;
    ((__nv_bfloat162*)hi)[i * 2 + 1] = hp1;
    ((__nv_bfloat162*)lo)[i * 2 + 0] = lp0;
    ((__nv_bfloat162*)lo)[i * 2 + 1] = lp1;
}

// ---------------------------------------------------------------------------
// Prepass: transpose + split.  in [K][N] fp32 -> out hi/lo [N][K] bf16.
// ---------------------------------------------------------------------------
__global__ __launch_bounds__(256) void tsplit_k(const float* __restrict__ in,
    __nv_bfloat16* __restrict__ hiT, __nv_bfloat16* __restrict__ loT, int K, int N)
{
    __shared__ float tile[32][33];
    const int n0 = blockIdx.x * 32, k0 = blockIdx.y * 32;
    const int tx = threadIdx.x, ty = threadIdx.y;
    for (int i = ty; i < 32; i += 8)
        tile[i][tx] = in[(size_t)(k0 + i) * N + n0 + tx];
    __syncthreads();
    for (int i = ty; i < 32; i += 8) {
        const float v = tile[tx][i];
        const __nv_bfloat16 h = __float2bfloat16(v);
        hiT[(size_t)(n0 + i) * K + k0 + tx] = h;
        loT[(size_t)(n0 + i) * K + k0 + tx] = __float2bfloat16(v - __bfloat162float(h));
    }
}

// ---------------------------------------------------------------------------
// mma.sync GEMM (unchanged from R4): C[128x128] = A @ B^T + bias, fp32 out.
// ---------------------------------------------------------------------------
#define GTILE_B   16384
#define GBUF_B    (4 * GTILE_B)
#define SMEM_GEMM (2 * GBUF_B)            // 131072

__global__ __launch_bounds__(256) void gemm_mma(
    const __nv_bfloat16* __restrict__ Ahi, const __nv_bfloat16* __restrict__ Alo,
    const __nv_bfloat16* __restrict__ Bhi, const __nv_bfloat16* __restrict__ Blo,
    const float* __restrict__ bias, float* __restrict__ Cc, int Ntot)
{
    extern __shared__ __align__(1024) char smg[];
    const uint32_t sb = smem_u32(smg);
    const int t = threadIdx.x, w = t >> 5, lane = t & 31;
    const int m0 = blockIdx.y << 7, n0 = blockIdx.x << 7;
    const int wm = (w >> 1) << 5, wn = (w & 1) << 6;

    const __nv_bfloat16* srcs[4] = {
        Ahi + (size_t)m0 * 1024, Alo + (size_t)m0 * 1024,
        Bhi + (size_t)n0 * 1024, Blo + (size_t)n0 * 1024 };

    float acc[2][8][4];
#pragma unroll
    for (int i = 0; i < 2; i++)
#pragma unroll
        for (int j = 0; j < 8; j++)
#pragma unroll
            for (int q = 0; q < 4; q++) acc[i][j][q] = 0.f;

    auto fill = [&](int c, int buf) {
        const int k0 = c << 6;
        const uint32_t bufb = sb + buf * GBUF_B;
#pragma unroll
        for (int tile = 0; tile < 4; ++tile) {
            const __nv_bfloat16* s = srcs[tile] + k0;
            const uint32_t db = bufb + tile * GTILE_B;
#pragma unroll
            for (int i = 0; i < 4; ++i) {
                const int idx = t + (i << 8);
                const int row = idx >> 3, seg = idx & 7;
                CP16(db + SWZ128(row * 128 + seg * 16),
                     s + (size_t)row * 1024 + seg * 8);
            }
        }
    };

    fill(0, 0);
    CP_COMMIT();
    CP_WAIT0();
    __syncthreads();

    const int aRow = wm + (lane & 15);
    const int bRow = wn + ((lane >> 4) << 3) + (lane & 7);

    for (int c = 0; c < 16; ++c) {
        const int buf = c & 1;
        if (c < 15) { fill(c + 1, buf ^ 1); CP_COMMIT(); }

        const uint32_t bA_h = sb + buf * GBUF_B;
        const uint32_t bA_l = bA_h + GTILE_B;
        const uint32_t bB_h = bA_h + 2 * GTILE_B;
        const uint32_t bB_l = bA_h + 3 * GTILE_B;

#pragma unroll
        for (int k16 = 0; k16 < 4; ++k16) {
            const int kbA = k16 * 32 + ((lane >> 4) & 1) * 16;
            const int kbB = k16 * 32 + ((lane >> 3) & 1) * 16;

            uint32_t aH[2][4], aL[2][4];
#pragma unroll
            for (int mi = 0; mi < 2; ++mi) {
                const uint32_t off = SWZ128((aRow + mi * 16) * 128 + kbA);
                ldsm4(aH[mi], bA_h + off);
                ldsm4(aL[mi], bA_l + off);
            }
            uint32_t bH[4][4], bL[4][4];
#pragma unroll
            for (int ni = 0; ni < 4; ++ni) {
                const uint32_t off = SWZ128((bRow + ni * 16) * 128 + kbB);
                ldsm4(bH[ni], bB_h + off);
                ldsm4(bL[ni], bB_l + off);
            }
#pragma unroll
            for (int mi = 0; mi < 2; ++mi)
#pragma unroll
                for (int ni = 0; ni < 4; ++ni)
#pragma unroll
                    for (int h2 = 0; h2 < 2; ++h2) {
                        float* d = acc[mi][ni * 2 + h2];
                        mma_bf16(d, aH[mi], &bH[ni][h2 * 2]);
                        mma_bf16(d, aH[mi], &bL[ni][h2 * 2]);
                        mma_bf16(d, aL[mi], &bH[ni][h2 * 2]);
                    }
        }
        CP_WAIT0();
        __syncthreads();
    }

    const int g2 = lane >> 2, tg = lane & 3;
#pragma unroll
    for (int mi = 0; mi < 2; ++mi) {
        const int row0 = m0 + wm + mi * 16 + g2;
#pragma unroll
        for (int j = 0; j < 8; ++j) {
            const int col = n0 + wn + j * 8 + tg * 2;
            const float2 b2 = *(const float2*)&bias[col];
            const float* d = acc[mi][j];
            float2 lo2 = { d[0] + b2.x, d[1] + b2.y };
            float2 hi2 = { d[2] + b2.x, d[3] + b2.y };
            *(float2*)&Cc[(size_t)row0 * Ntot + col] = lo2;
            *(float2*)&Cc[(size_t)(row0 + 8) * Ntot + col] = hi2;
        }
    }
}

// ---------------------------------------------------------------------------
// Flash attention with mma.sync bf16 split precision.
// CTA = 128 queries x one (b,h); 8 warps x 16 rows. Key tiles of 64.
// S = Qh*Kh + Qh*Kl + Ql*Kh (fp32 accum); softmax fp32 in registers;
// P split hi/lo in registers (acc frag == A frag layout); O += Ph*Vh+Ph*Vl+Pl*Vh.
// V stored transposed [d][key] in smem so PV B-operand uses the same
// non-trans ldmatrix pattern as the GEMM. Output written as hi/lo bf16 split.
// Smem: Qh,Ql[128][64] + Kh,Kl[64][64] + VTh,VTl[64][64] = 65536 B.
// ---------------------------------------------------------------------------
#define SMEM_ATT2 65536

__global__ __launch_bounds__(256) void attn_mma(
    const float* __restrict__ qkv,
    __nv_bfloat16* __restrict__ ohi, __nv_bfloat16* __restrict__ olo)
{
    extern __shared__ __align__(1024) char sma[];
    const uint32_t sb  = smem_u32(sma);
    const uint32_t sQh = sb, sQl = sb + 16384;
    const uint32_t sKh = sb + 32768, sKl = sb + 40960;
    const uint32_t sVh = sb + 49152, sVl = sb + 57344;
    char* pQh = sma;          char* pQl = sma + 16384;
    char* pKh = sma + 32768;  char* pKl = sma + 40960;
    char* pVh = sma + 49152;  char* pVl = sma + 57344;

    const int t = threadIdx.x, w = t >> 5, lane = t & 31;
    const int g = lane >> 2, tq = lane & 3;
    const int qi = gridDim.x - 1 - blockIdx.x;      // heavy tiles first
    const int bh = blockIdx.y, b = bh >> 4, h = bh & 15;
    const int qbase = qi << 7;
    const size_t brow = (size_t)b * TT;
    const int wm = w << 4;

    // Load + scale + split Q tile [128][64]
    for (int idx = t; idx < 2048; idx += 256) {
        const int r = idx >> 4, d4 = (idx & 15) << 2;
        const float4 v = *(const float4*)&qkv[(brow + qbase + r) * C3 + h * 64 + d4];
        float f0 = v.x * 0.125f, f1 = v.y * 0.125f, f2 = v.z * 0.125f, f3 = v.w * 0.125f;
        float h0 = __bfloat162float(__float2bfloat16(f0));
        float h1 = __bfloat162float(__float2bfloat16(f1));
        float h2 = __bfloat162float(__float2bfloat16(f2));
        float h3 = __bfloat162float(__float2bfloat16(f3));
        const uint32_t off = SWZ128(r * 128 + d4 * 2);
        *(uint2*)(pQh + off) = make_uint2(pack_bf16(f0, f1), pack_bf16(f2, f3));
        *(uint2*)(pQl + off) = make_uint2(pack_bf16(f0 - h0, f1 - h1),
                                          pack_bf16(f2 - h2, f3 - h3));
    }

    float oacc[8][4];
#pragma unroll
    for (int j = 0; j < 8; ++j)
#pragma unroll
        for (int q = 0; q < 4; ++q) oacc[j][q] = 0.f;
    float mrow[2] = { -1e30f, -1e30f };
    float lrow[2] = { 0.f, 0.f };

    const int aRow  = wm + (lane & 15);
    const int bRowS = ((lane >> 4) << 3) + (lane & 7);
    const int ntiles = 2 * qi + 2;

    for (int kt = 0; kt < ntiles; ++kt) {
        const int kb = kt << 6;
        __syncthreads();
        // Fill K (K-major) and V (transposed) tiles, split hi/lo
        for (int idx = t; idx < 1024; idx += 256) {
            const int r = idx >> 4, d4 = (idx & 15) << 2;
            const size_t gaddr = (brow + kb + r) * C3 + C_DIM + h * 64 + d4;
            const float4 kv = *(const float4*)&qkv[gaddr];
            float kh0 = __bfloat162float(__float2bfloat16(kv.x));
            float kh1 = __bfloat162float(__float2bfloat16(kv.y));
            float kh2 = __bfloat162float(__float2bfloat16(kv.z));
            float kh3 = __bfloat162float(__float2bfloat16(kv.w));
            const uint32_t offk = SWZ128(r * 128 + d4 * 2);
            *(uint2*)(pKh + offk) = make_uint2(pack_bf16(kv.x, kv.y), pack_bf16(kv.z, kv.w));
            *(uint2*)(pKl + offk) = make_uint2(pack_bf16(kv.x - kh0, kv.y - kh1),
                                               pack_bf16(kv.z - kh2, kv.w - kh3));
            const float4 vv = *(const float4*)&qkv[gaddr + C_DIM];
            const float vf[4] = { vv.x, vv.y, vv.z, vv.w };
#pragma unroll
            for (int u = 0; u < 4; ++u) {
                const __nv_bfloat16 vh = __float2bfloat16(vf[u]);
                const uint32_t offv = SWZ128((d4 + u) * 128 + r * 2);
                *(__nv_bfloat16*)(pVh + offv) = vh;
                *(__nv_bfloat16*)(pVl + offv) =
                    __float2bfloat16(vf[u] - __bfloat162float(vh));
            }
        }
        __syncthreads();

        // ---- S = Q K^T (split, fp32 accum) ----
        float sacc[8][4];
#pragma unroll
        for (int j = 0; j < 8; ++j)
#pragma unroll
            for (int q = 0; q < 4; ++q) sacc[j][q] = 0.f;

#pragma unroll
        for (int k16 = 0; k16 < 4; ++k16) {
            const int kbA = k16 * 32 + ((lane >> 4) & 1) * 16;
            const int kbB = k16 * 32 + ((lane >> 3) & 1) * 16;
            uint32_t aH[4], aL[4];
            const uint32_t offA = SWZ128(aRow * 128 + kbA);
            ldsm4(aH, sQh + offA);
            ldsm4(aL, sQl + offA);
            uint32_t bH[4][4], bL[4][4];
#pragma unroll
            for (int ni = 0; ni < 4; ++ni) {
                const uint32_t off = SWZ128((bRowS + ni * 16) * 128 + kbB);
                ldsm4(bH[ni], sKh + off);
                ldsm4(bL[ni], sKl + off);
            }
#pragma unroll
            for (int ni = 0; ni < 4; ++ni)
#pragma unroll
                for (int h2 = 0; h2 < 2; ++h2) {
                    float* d = sacc[ni * 2 + h2];
                    mma_bf16(d, aH, &bH[ni][h2 * 2]);
                    mma_bf16(d, aH, &bL[ni][h2 * 2]);
                    mma_bf16(d, aL, &bH[ni][h2 * 2]);
                }
        }

        // ---- causal mask (only last two tiles can cross the diagonal) ----
        if (kt >= 2 * qi) {
            const int row0 = qbase + wm + g;
#pragma unroll
            for (int j = 0; j < 8; ++j) {
                const int col = kb + j * 8 + tq * 2;
                if (col     > row0)     sacc[j][0] = -1e30f;
                if (col + 1 > row0)     sacc[j][1] = -1e30f;
                if (col     > row0 + 8) sacc[j][2] = -1e30f;
                if (col + 1 > row0 + 8) sacc[j][3] = -1e30f;
            }
        }

        // ---- online softmax (2 rows/thread, quad reductions) ----
#pragma unroll
        for (int rr = 0; rr < 2; ++rr) {
            const int i0 = rr * 2;
            float mt = -1e30f;
#pragma unroll
            for (int j = 0; j < 8; ++j)
                mt = fmaxf(mt, fmaxf(sacc[j][i0], sacc[j][i0 + 1]));
            mt = fmaxf(mt, __shfl_xor_sync(0xffffffffu, mt, 1));
            mt = fmaxf(mt, __shfl_xor_sync(0xffffffffu, mt, 2));
            const float mn = fmaxf(mrow[rr], mt);
            const float alpha = __expf(mrow[rr] - mn);
            mrow[rr] = mn;
            float ps = 0.f;
#pragma unroll
            for (int j = 0; j < 8; ++j) {
                const float p0 = __expf(sacc[j][i0] - mn);
                const float p1 = __expf(sacc[j][i0 + 1] - mn);
                sacc[j][i0] = p0; sacc[j][i0 + 1] = p1;
                ps += p0 + p1;
            }
            ps += __shfl_xor_sync(0xffffffffu, ps, 1);
            ps += __shfl_xor_sync(0xffffffffu, ps, 2);
            lrow[rr] = lrow[rr] * alpha + ps;
#pragma unroll
            for (int j = 0; j < 8; ++j) {
                oacc[j][i0] *= alpha;
                oacc[j][i0 + 1] *= alpha;
            }
        }

        // ---- O += P V (P split from S accumulators, register-direct) ----
#pragma unroll
        for (int kk = 0; kk < 4; ++kk) {
            const float* s0 = sacc[2 * kk];
            const float* s1 = sacc[2 * kk + 1];
            uint32_t aPh[4], aPl[4];
            {
                float h00 = __bfloat162float(__float2bfloat16(s0[0]));
                float h01 = __bfloat162float(__float2bfloat16(s0[1]));
                float h02 = __bfloat162float(__float2bfloat16(s0[2]));
                float h03 = __bfloat162float(__float2bfloat16(s0[3]));
                float h10 = __bfloat162float(__float2bfloat16(s1[0]));
                float h11 = __bfloat162float(__float2bfloat16(s1[1]));
                float h12 = __bfloat162float(__float2bfloat16(s1[2]));
                float h13 = __bfloat162float(__float2bfloat16(s1[3]));
                aPh[0] = pack_bf16(s0[0], s0[1]);
                aPh[1] = pack_bf16(s0[2], s0[3]);
                aPh[2] = pack_bf16(s1[0], s1[1]);
                aPh[3] = pack_bf16(s1[2], s1[3]);
                aPl[0] = pack_bf16(s0[0] - h00, s0[1] - h01);
                aPl[1] = pack_bf16(s0[2] - h02, s0[3] - h03);
                aPl[2] = pack_bf16(s1[0] - h10, s1[1] - h11);
                aPl[3] = pack_bf16(s1[2] - h12, s1[3] - h13);
            }
            const int kbB = kk * 32 + ((lane >> 3) & 1) * 16;
            uint32_t vH[4][4], vL[4][4];
#pragma unroll
            for (int ni = 0; ni < 4; ++ni) {
                const uint32_t off = SWZ128((bRowS + ni * 16) * 128 + kbB);
                ldsm4(vH[ni], sVh + off);
                ldsm4(vL[ni], sVl + off);
            }
#pragma unroll
            for (int ni = 0; ni < 4; ++ni)
#pragma unroll
                for (int h2 = 0; h2 < 2; ++h2) {
                    float* d = oacc[ni * 2 + h2];
                    mma_bf16(d, aPh, &vH[ni][h2 * 2]);
                    mma_bf16(d, aPh, &vL[ni][h2 * 2]);
                    mma_bf16(d, aPl, &vH[ni][h2 * 2]);
                }
        }
    }

    // ---- epilogue: normalize, split hi/lo, store (K-major [M][1024]) ----
    const float inv0 = 1.f / lrow[0];
    const float inv1 = 1.f / lrow[1];
    const int row0 = qbase + wm + g;
#pragma unroll
    for (int j = 0; j < 8; ++j) {
        const int col = h * 64 + j * 8 + tq * 2;
        const float v0 = oacc[j][0] * inv0, v1 = oacc[j][1] * inv0;
        const float v2 = oacc[j][2] * inv1, v3 = oacc[j][3] * inv1;
        const float e0 = __bfloat162float(__float2bfloat16(v0));
        const float e1 = __bfloat162float(__float2bfloat16(v1));
        const float e2 = __bfloat162float(__float2bfloat16(v2));
        const float e3 = __bfloat162float(__float2bfloat16(v3));
        const size_t o0 = (brow + row0) * C_DIM + col;
        const size_t o1 = (brow + row0 + 8) * C_DIM + col;
        *(uint32_t*)&ohi[o0] = pack_bf16(v0, v1);
        *(uint32_t*)&olo[o0] = pack_bf16(v0 - e0, v1 - e1);
        *(uint32_t*)&ohi[o1] = pack_bf16(v2, v3);
        *(uint32_t*)&olo[o1] = pack_bf16(v2 - e2, v3 - e3);
    }
}

// ---------------------------------------------------------------------------
extern "C" void kernel_launch(void* const* d_in, const int* in_sizes, int n_in,
                              void* d_out, int out_size)
{
    const float* x      = (const float*)d_in[0];
    const float* qkv_w  = (const float*)d_in[1];
    const float* qkv_b  = (const float*)d_in[2];
    const float* out_w  = (const float*)d_in[3];
    const float* out_b  = (const float*)d_in[4];
    float* out = (float*)d_out;

    float* qkv_buf;
    __nv_bfloat16 *xhi, *xlo, *ahi, *alo, *wqh, *wql, *woh, *wol;
    cudaGetSymbolAddress((void**)&qkv_buf, g_qkv);
    cudaGetSymbolAddress((void**)&xhi, g_xhi);
    cudaGetSymbolAddress((void**)&xlo, g_xlo);
    cudaGetSymbolAddress((void**)&ahi, g_ahi);
    cudaGetSymbolAddress((void**)&alo, g_alo);
    cudaGetSymbolAddress((void**)&wqh, g_wqt_hi);
    cudaGetSymbolAddress((void**)&wql, g_wqt_lo);
    cudaGetSymbolAddress((void**)&woh, g_wot_hi);
    cudaGetSymbolAddress((void**)&wol, g_wot_lo);

    cudaFuncSetAttribute(gemm_mma, cudaFuncAttributeMaxDynamicSharedMemorySize, SMEM_GEMM);
    cudaFuncSetAttribute(attn_mma, cudaFuncAttributeMaxDynamicSharedMemorySize, SMEM_ATT2);

    // Prepasses: split x; transpose+split weights
    split_k<<<(MTOT * C_DIM / 4 + 255) / 256, 256>>>(x, xhi, xlo, MTOT * C_DIM / 4);
    tsplit_k<<<dim3(C3 / 32, C_DIM / 32), dim3(32, 8)>>>(qkv_w, wqh, wql, C_DIM, C3);
    tsplit_k<<<dim3(C_DIM / 32, C_DIM / 32), dim3(32, 8)>>>(out_w, woh, wol, C_DIM, C_DIM);

    // 1) QKV projection (mma.sync bf16 split)
    gemm_mma<<<dim3(C3 / 128, MTOT / 128), 256, SMEM_GEMM>>>(
        xhi, xlo, wqh, wql, qkv_b, qkv_buf, C3);

    // 2) Causal MHA (mma.sync bf16 split; writes hi/lo split output directly)
    attn_mma<<<dim3(TT / 128, BB * HH), 256, SMEM_ATT2>>>(qkv_buf, ahi, alo);

    // 3) Output projection (mma.sync bf16 split)
    gemm_mma<<<dim3(C_DIM / 128, MTOT / 128), 256, SMEM_GEMM>>>(
        ahi, alo, woh, wol, out_b, out, C_DIM);
}

// round 6
// speedup vs baseline: 2.9640x; 1.2616x over previous
#include <cuda_runtime.h>
#include <cuda_bf16.h>
#include <cstdint>

#define C_DIM 1024
#define C3    3072
#define BB    2
#define TT    2048
#define HH    16
#define MTOT  4096   // BB*TT

// ---------------------------------------------------------------------------
// Scratch buffers (__device__ globals: the sanctioned no-alloc workaround)
// ---------------------------------------------------------------------------
__device__ __nv_bfloat16 g_qkvh[(size_t)MTOT * C3];     // QKV split hi (Q pre-scaled)
__device__ __nv_bfloat16 g_qkvl[(size_t)MTOT * C3];     // QKV split lo
__device__ __nv_bfloat16 g_xhi[(size_t)MTOT * C_DIM];
__device__ __nv_bfloat16 g_xlo[(size_t)MTOT * C_DIM];
__device__ __nv_bfloat16 g_ahi[(size_t)MTOT * C_DIM];   // attn out hi (K-major)
__device__ __nv_bfloat16 g_alo[(size_t)MTOT * C_DIM];   // attn out lo
__device__ __nv_bfloat16 g_wqt_hi[(size_t)C3 * C_DIM];  // qkv_w^T [N=3072][K=1024]
__device__ __nv_bfloat16 g_wqt_lo[(size_t)C3 * C_DIM];
__device__ __nv_bfloat16 g_wot_hi[(size_t)C_DIM * C_DIM];
__device__ __nv_bfloat16 g_wot_lo[(size_t)C_DIM * C_DIM];

// ---------------------------------------------------------------------------
// Portable tensor-core helpers (compute_103-safe: ldmatrix / mma.sync / cp.async)
// ---------------------------------------------------------------------------
__device__ __forceinline__ uint32_t smem_u32(const void* p) {
    uint32_t a;
    asm("{ .reg .u64 t; cvta.to.shared.u64 t, %1; cvt.u32.u64 %0, t; }"
        : "=r"(a) : "l"(p));
    return a;
}
#define SWZ128(off) ((off) ^ (((off) >> 3) & 0x70))

__device__ __forceinline__ void ldsm4(uint32_t* r, uint32_t addr) {
    asm volatile("ldmatrix.sync.aligned.m8n8.x4.shared.b16 {%0,%1,%2,%3}, [%4];"
        : "=r"(r[0]), "=r"(r[1]), "=r"(r[2]), "=r"(r[3]) : "r"(addr));
}
__device__ __forceinline__ void ldsm4t(uint32_t* r, uint32_t addr) {
    asm volatile("ldmatrix.sync.aligned.m8n8.x4.trans.shared.b16 {%0,%1,%2,%3}, [%4];"
        : "=r"(r[0]), "=r"(r[1]), "=r"(r[2]), "=r"(r[3]) : "r"(addr));
}
__device__ __forceinline__ void mma_bf16(float* d, const uint32_t* a, const uint32_t* b) {
    asm volatile("mma.sync.aligned.m16n8k16.row.col.f32.bf16.bf16.f32 "
        "{%0,%1,%2,%3}, {%4,%5,%6,%7}, {%8,%9}, {%0,%1,%2,%3};"
        : "+f"(d[0]), "+f"(d[1]), "+f"(d[2]), "+f"(d[3])
        : "r"(a[0]), "r"(a[1]), "r"(a[2]), "r"(a[3]), "r"(b[0]), "r"(b[1]));
}
#define CP16(dst, src)  asm volatile("cp.async.cg.shared.global [%0], [%1], 16;" :: "r"(dst), "l"(src) : "memory")
#define CP_COMMIT()     asm volatile("cp.async.commit_group;" ::: "memory")
#define CP_WAIT0()      asm volatile("cp.async.wait_group 0;" ::: "memory")
#define CP_WAIT1()      asm volatile("cp.async.wait_group 1;" ::: "memory")

__device__ __forceinline__ uint32_t pack_bf16(float a, float b) {
    __nv_bfloat162 p;
    p.x = __float2bfloat16(a);
    p.y = __float2bfloat16(b);
    return *(uint32_t*)&p;
}

// ---------------------------------------------------------------------------
// Prepass: fp32 -> (hi, lo) bf16 split.  n4 = element_count/4.
// ---------------------------------------------------------------------------
__global__ __launch_bounds__(256) void split_k(const float* __restrict__ in,
    __nv_bfloat16* __restrict__ hi, __nv_bfloat16* __restrict__ lo, int n4)
{
    const int i = blockIdx.x * 256 + threadIdx.x;
    if (i >= n4) return;
    const float4 v = ((const float4*)in)[i];
    __nv_bfloat16 h0 = __float2bfloat16(v.x), h1 = __float2bfloat16(v.y);
    __nv_bfloat16 h2 = __float2bfloat16(v.z), h3 = __float2bfloat16(v.w);
    __nv_bfloat162 hp0, hp1, lp0, lp1;
    hp0.x = h0; hp0.y = h1; hp1.x = h2; hp1.y = h3;
    lp0.x = __float2bfloat16(v.x - __bfloat162float(h0));
    lp0.y = __float2bfloat16(v.y - __bfloat162float(h1));
    lp1.x = __float2bfloat16(v.z - __bfloat162float(h2));
    lp1.y = __float2bfloat16(v.w - __bfloat162float(h3));
    ((__nv_bfloat162*)hi)[i * 2 + 0] = hp0;
    ((__nv_bfloat162*)hi)[i * 2 + 1] = hp1;
    ((__nv_bfloat162*)lo)[i * 2 + 0] = lp0;
    ((__nv_bfloat162*)lo)[i * 2 + 1] = lp1;
}

// ---------------------------------------------------------------------------
// Prepass: transpose + split.  in [K][N] fp32 -> out hi/lo [N][K] bf16.
// ---------------------------------------------------------------------------
__global__ __launch_bounds__(256) void tsplit_k(const float* __restrict__ in,
    __nv_bfloat16* __restrict__ hiT, __nv_bfloat16* __restrict__ loT, int K, int N)
{
    __shared__ float tile[32][33];
    const int n0 = blockIdx.x * 32, k0 = blockIdx.y * 32;
    const int tx = threadIdx.x, ty = threadIdx.y;
    for (int i = ty; i < 32; i += 8)
        tile[i][tx] = in[(size_t)(k0 + i) * N + n0 + tx];
    __syncthreads();
    for (int i = ty; i < 32; i += 8) {
        const float v = tile[tx][i];
        const __nv_bfloat16 h = __float2bfloat16(v);
        hiT[(size_t)(n0 + i) * K + k0 + tx] = h;
        loT[(size_t)(n0 + i) * K + k0 + tx] = __float2bfloat16(v - __bfloat162float(h));
    }
}

// ---------------------------------------------------------------------------
// mma.sync GEMM: C[128x128] = A @ B^T + bias.
// mode 0: fp32 output to Cf.  mode 1: hi/lo bf16 split output to Chi/Clo,
//         with cols < C_DIM (the Q block) pre-scaled by 1/sqrt(Dh)=0.125.
// ---------------------------------------------------------------------------
#define GTILE_B   16384
#define GBUF_B    (4 * GTILE_B)
#define SMEM_GEMM (2 * GBUF_B)            // 131072

__global__ __launch_bounds__(256) void gemm_mma(
    const __nv_bfloat16* __restrict__ Ahi, const __nv_bfloat16* __restrict__ Alo,
    const __nv_bfloat16* __restrict__ Bhi, const __nv_bfloat16* __restrict__ Blo,
    const float* __restrict__ bias, float* __restrict__ Cf,
    __nv_bfloat16* __restrict__ Chi, __nv_bfloat16* __restrict__ Clo,
    int Ntot, int mode)
{
    extern __shared__ __align__(1024) char smg[];
    const uint32_t sb = smem_u32(smg);
    const int t = threadIdx.x, w = t >> 5, lane = t & 31;
    const int m0 = blockIdx.y << 7, n0 = blockIdx.x << 7;
    const int wm = (w >> 1) << 5, wn = (w & 1) << 6;

    const __nv_bfloat16* srcs[4] = {
        Ahi + (size_t)m0 * 1024, Alo + (size_t)m0 * 1024,
        Bhi + (size_t)n0 * 1024, Blo + (size_t)n0 * 1024 };

    float acc[2][8][4];
#pragma unroll
    for (int i = 0; i < 2; i++)
#pragma unroll
        for (int j = 0; j < 8; j++)
#pragma unroll
            for (int q = 0; q < 4; q++) acc[i][j][q] = 0.f;

    auto fill = [&](int c, int buf) {
        const int k0 = c << 6;
        const uint32_t bufb = sb + buf * GBUF_B;
#pragma unroll
        for (int tile = 0; tile < 4; ++tile) {
            const __nv_bfloat16* s = srcs[tile] + k0;
            const uint32_t db = bufb + tile * GTILE_B;
#pragma unroll
            for (int i = 0; i < 4; ++i) {
                const int idx = t + (i << 8);
                const int row = idx >> 3, seg = idx & 7;
                CP16(db + SWZ128(row * 128 + seg * 16),
                     s + (size_t)row * 1024 + seg * 8);
            }
        }
    };

    fill(0, 0);
    CP_COMMIT();
    CP_WAIT0();
    __syncthreads();

    const int aRow = wm + (lane & 15);
    const int bRow = wn + ((lane >> 4) << 3) + (lane & 7);

    for (int c = 0; c < 16; ++c) {
        const int buf = c & 1;
        if (c < 15) { fill(c + 1, buf ^ 1); CP_COMMIT(); }

        const uint32_t bA_h = sb + buf * GBUF_B;
        const uint32_t bA_l = bA_h + GTILE_B;
        const uint32_t bB_h = bA_h + 2 * GTILE_B;
        const uint32_t bB_l = bA_h + 3 * GTILE_B;

#pragma unroll
        for (int k16 = 0; k16 < 4; ++k16) {
            const int kbA = k16 * 32 + ((lane >> 4) & 1) * 16;
            const int kbB = k16 * 32 + ((lane >> 3) & 1) * 16;

            uint32_t aH[2][4], aL[2][4];
#pragma unroll
            for (int mi = 0; mi < 2; ++mi) {
                const uint32_t off = SWZ128((aRow + mi * 16) * 128 + kbA);
                ldsm4(aH[mi], bA_h + off);
                ldsm4(aL[mi], bA_l + off);
            }
            uint32_t bH[4][4], bL[4][4];
#pragma unroll
            for (int ni = 0; ni < 4; ++ni) {
                const uint32_t off = SWZ128((bRow + ni * 16) * 128 + kbB);
                ldsm4(bH[ni], bB_h + off);
                ldsm4(bL[ni], bB_l + off);
            }
#pragma unroll
            for (int mi = 0; mi < 2; ++mi)
#pragma unroll
                for (int ni = 0; ni < 4; ++ni)
#pragma unroll
                    for (int h2 = 0; h2 < 2; ++h2) {
                        float* d = acc[mi][ni * 2 + h2];
                        mma_bf16(d, aH[mi], &bH[ni][h2 * 2]);
                        mma_bf16(d, aH[mi], &bL[ni][h2 * 2]);
                        mma_bf16(d, aL[mi], &bH[ni][h2 * 2]);
                    }
        }
        CP_WAIT0();
        __syncthreads();
    }

    const int g2 = lane >> 2, tg = lane & 3;
    if (mode == 0) {
#pragma unroll
        for (int mi = 0; mi < 2; ++mi) {
            const int row0 = m0 + wm + mi * 16 + g2;
#pragma unroll
            for (int j = 0; j < 8; ++j) {
                const int col = n0 + wn + j * 8 + tg * 2;
                const float2 b2 = *(const float2*)&bias[col];
                const float* d = acc[mi][j];
                float2 lo2 = { d[0] + b2.x, d[1] + b2.y };
                float2 hi2 = { d[2] + b2.x, d[3] + b2.y };
                *(float2*)&Cf[(size_t)row0 * Ntot + col] = lo2;
                *(float2*)&Cf[(size_t)(row0 + 8) * Ntot + col] = hi2;
            }
        }
    } else {
        const float scale = (n0 < C_DIM) ? 0.125f : 1.0f;   // Q block pre-scale
#pragma unroll
        for (int mi = 0; mi < 2; ++mi) {
            const int row0 = m0 + wm + mi * 16 + g2;
#pragma unroll
            for (int j = 0; j < 8; ++j) {
                const int col = n0 + wn + j * 8 + tg * 2;
                const float2 b2 = *(const float2*)&bias[col];
                const float* d = acc[mi][j];
                const float v0 = (d[0] + b2.x) * scale, v1 = (d[1] + b2.y) * scale;
                const float v2 = (d[2] + b2.x) * scale, v3 = (d[3] + b2.y) * scale;
                const float e0 = __bfloat162float(__float2bfloat16(v0));
                const float e1 = __bfloat162float(__float2bfloat16(v1));
                const float e2 = __bfloat162float(__float2bfloat16(v2));
                const float e3 = __bfloat162float(__float2bfloat16(v3));
                const size_t o0 = (size_t)row0 * Ntot + col;
                const size_t o1 = (size_t)(row0 + 8) * Ntot + col;
                *(uint32_t*)&Chi[o0] = pack_bf16(v0, v1);
                *(uint32_t*)&Clo[o0] = pack_bf16(v0 - e0, v1 - e1);
                *(uint32_t*)&Chi[o1] = pack_bf16(v2, v3);
                *(uint32_t*)&Clo[o1] = pack_bf16(v2 - e2, v3 - e3);
            }
        }
    }
}

// ---------------------------------------------------------------------------
// Flash attention v2: all-bf16-split inputs via cp.async, double-buffered K/V,
// Q fragments hoisted to registers, V row-major + ldmatrix.trans for PV.
// CTA = 128 queries x one (b,h); 8 warps x 16 rows; key tiles of 64.
// Smem: Qh,Ql[128][64] (32KB) + 2 stages x {Kh,Kl,Vh,Vl}[64][64] (64KB) = 96KB.
// ---------------------------------------------------------------------------
#define SMEM_ATT2 98304

__global__ __launch_bounds__(256) void attn_mma(
    const __nv_bfloat16* __restrict__ qh, const __nv_bfloat16* __restrict__ ql,
    __nv_bfloat16* __restrict__ ohi, __nv_bfloat16* __restrict__ olo)
{
    extern __shared__ __align__(1024) char sma[];
    const uint32_t sb  = smem_u32(sma);
    const uint32_t sQh = sb, sQl = sb + 16384;

    const int t = threadIdx.x, w = t >> 5, lane = t & 31;
    const int g = lane >> 2, tq = lane & 3;
    const int qi = gridDim.x - 1 - blockIdx.x;      // heavy tiles first
    const int bh = blockIdx.y, b = bh >> 4, h = bh & 15;
    const int qbase = qi << 7;
    const size_t brow = (size_t)b * TT;
    const int wm = w << 4;
    const int hcol = h * 64;

    // ---- cp.async fills ----
    auto fillQ = [&]() {
#pragma unroll
        for (int i = 0; i < 8; ++i) {
            const int idx = t + (i << 8);            // 0..2047
            const int arr = idx >> 10;               // 0 hi, 1 lo
            const int r = (idx >> 3) & 127, seg = idx & 7;
            const __nv_bfloat16* src =
                (arr ? ql : qh) + (brow + qbase + r) * C3 + hcol + seg * 8;
            CP16((arr ? sQl : sQh) + SWZ128(r * 128 + seg * 16), src);
        }
    };
    auto fillKV = [&](int kt, int buf) {
        const int kb = kt << 6;
        const uint32_t sbase = sb + 32768 + buf * 32768;
#pragma unroll
        for (int i = 0; i < 8; ++i) {
            const int idx = t + (i << 8);            // 0..2047
            const int arr = idx >> 9;                // 0 Kh, 1 Kl, 2 Vh, 3 Vl
            const int r = (idx >> 3) & 63, seg = idx & 7;
            const int colbase = ((arr < 2) ? C_DIM : 2 * C_DIM) + hcol;
            const __nv_bfloat16* src =
                ((arr & 1) ? ql : qh) + (brow + kb + r) * C3 + colbase + seg * 8;
            CP16(sbase + arr * 8192 + SWZ128(r * 128 + seg * 16), src);
        }
    };

    float oacc[8][4];
#pragma unroll
    for (int j = 0; j < 8; ++j)
#pragma unroll
        for (int q = 0; q < 4; ++q) oacc[j][q] = 0.f;
    float mrow[2] = { -1e30f, -1e30f };
    float lrow[2] = { 0.f, 0.f };

    const int aRow  = wm + (lane & 15);
    const int bRowS = ((lane >> 4) << 3) + (lane & 7);
    const int ntiles = 2 * qi + 2;

    uint32_t aQh[4][4], aQl[4][4];                   // Q frags, hoisted

    fillQ();
    fillKV(0, 0);
    CP_COMMIT();

    for (int kt = 0; kt < ntiles; ++kt) {
        const int kb = kt << 6;
        const uint32_t sKh = sb + 32768 + (kt & 1) * 32768;
        const uint32_t sKl = sKh + 8192, sVh = sKh + 16384, sVl = sKh + 24576;

        if (kt + 1 < ntiles) {
            fillKV(kt + 1, (kt + 1) & 1);
            CP_COMMIT();
            CP_WAIT1();
        } else {
            CP_WAIT0();
        }
        __syncthreads();

        if (kt == 0) {
#pragma unroll
            for (int k16 = 0; k16 < 4; ++k16) {
                const int kbA = k16 * 32 + ((lane >> 4) & 1) * 16;
                const uint32_t offA = SWZ128(aRow * 128 + kbA);
                ldsm4(aQh[k16], sQh + offA);
                ldsm4(aQl[k16], sQl + offA);
            }
        }

        // ---- S = Q K^T (split, fp32 accum) ----
        float sacc[8][4];
#pragma unroll
        for (int j = 0; j < 8; ++j)
#pragma unroll
            for (int q = 0; q < 4; ++q) sacc[j][q] = 0.f;

#pragma unroll
        for (int k16 = 0; k16 < 4; ++k16) {
            const int kbB = k16 * 32 + ((lane >> 3) & 1) * 16;
            uint32_t bH[4][4], bL[4][4];
#pragma unroll
            for (int ni = 0; ni < 4; ++ni) {
                const uint32_t off = SWZ128((bRowS + ni * 16) * 128 + kbB);
                ldsm4(bH[ni], sKh + off);
                ldsm4(bL[ni], sKl + off);
            }
#pragma unroll
            for (int ni = 0; ni < 4; ++ni)
#pragma unroll
                for (int h2 = 0; h2 < 2; ++h2) {
                    float* d = sacc[ni * 2 + h2];
                    mma_bf16(d, aQh[k16], &bH[ni][h2 * 2]);
                    mma_bf16(d, aQh[k16], &bL[ni][h2 * 2]);
                    mma_bf16(d, aQl[k16], &bH[ni][h2 * 2]);
                }
        }

        // ---- causal mask (only last two tiles cross the diagonal) ----
        if (kt >= 2 * qi) {
            const int row0 = qbase + wm + g;
#pragma unroll
            for (int j = 0; j < 8; ++j) {
                const int col = kb + j * 8 + tq * 2;
                if (col     > row0)     sacc[j][0] = -1e30f;
                if (col + 1 > row0)     sacc[j][1] = -1e30f;
                if (col     > row0 + 8) sacc[j][2] = -1e30f;
                if (col + 1 > row0 + 8) sacc[j][3] = -1e30f;
            }
        }

        // ---- online softmax (2 rows/thread, quad reductions) ----
#pragma unroll
        for (int rr = 0; rr < 2; ++rr) {
            const int i0 = rr * 2;
            float mt = -1e30f;
#pragma unroll
            for (int j = 0; j < 8; ++j)
                mt = fmaxf(mt, fmaxf(sacc[j][i0], sacc[j][i0 + 1]));
            mt = fmaxf(mt, __shfl_xor_sync(0xffffffffu, mt, 1));
            mt = fmaxf(mt, __shfl_xor_sync(0xffffffffu, mt, 2));
            const float mn = fmaxf(mrow[rr], mt);
            const float alpha = __expf(mrow[rr] - mn);
            mrow[rr] = mn;
            float ps = 0.f;
#pragma unroll
            for (int j = 0; j < 8; ++j) {
                const float p0 = __expf(sacc[j][i0] - mn);
                const float p1 = __expf(sacc[j][i0 + 1] - mn);
                sacc[j][i0] = p0; sacc[j][i0 + 1] = p1;
                ps += p0 + p1;
            }
            ps += __shfl_xor_sync(0xffffffffu, ps, 1);
            ps += __shfl_xor_sync(0xffffffffu, ps, 2);
            lrow[rr] = lrow[rr] * alpha + ps;
#pragma unroll
            for (int j = 0; j < 8; ++j) {
                oacc[j][i0] *= alpha;
                oacc[j][i0 + 1] *= alpha;
            }
        }

        // ---- O += P V (P split register-direct; V via ldmatrix.trans) ----
#pragma unroll
        for (int kk = 0; kk < 4; ++kk) {
            const float* s0 = sacc[2 * kk];
            const float* s1 = sacc[2 * kk + 1];
            uint32_t aPh[4], aPl[4];
            {
                float h00 = __bfloat162float(__float2bfloat16(s0[0]));
                float h01 = __bfloat162float(__float2bfloat16(s0[1]));
                float h02 = __bfloat162float(__float2bfloat16(s0[2]));
                float h03 = __bfloat162float(__float2bfloat16(s0[3]));
                float h10 = __bfloat162float(__float2bfloat16(s1[0]));
                float h11 = __bfloat162float(__float2bfloat16(s1[1]));
                float h12 = __bfloat162float(__float2bfloat16(s1[2]));
                float h13 = __bfloat162float(__float2bfloat16(s1[3]));
                aPh[0] = pack_bf16(s0[0], s0[1]);
                aPh[1] = pack_bf16(s0[2], s0[3]);
                aPh[2] = pack_bf16(s1[0], s1[1]);
                aPh[3] = pack_bf16(s1[2], s1[3]);
                aPl[0] = pack_bf16(s0[0] - h00, s0[1] - h01);
                aPl[1] = pack_bf16(s0[2] - h02, s0[3] - h03);
                aPl[2] = pack_bf16(s1[0] - h10, s1[1] - h11);
                aPl[3] = pack_bf16(s1[2] - h12, s1[3] - h13);
            }
            // V fragments: row = key (kk*16 + lane&15), col = d, trans load
            const int vr = kk * 16 + (lane & 15);
            const int vc = ((lane >> 4) & 1) * 16;
            uint32_t vH[4][4], vL[4][4];
#pragma unroll
            for (int ni = 0; ni < 4; ++ni) {
                const uint32_t off = SWZ128(vr * 128 + ni * 32 + vc);
                ldsm4t(vH[ni], sVh + off);
                ldsm4t(vL[ni], sVl + off);
            }
#pragma unroll
            for (int ni = 0; ni < 4; ++ni)
#pragma unroll
                for (int h2 = 0; h2 < 2; ++h2) {
                    float* d = oacc[ni * 2 + h2];
                    mma_bf16(d, aPh, &vH[ni][h2 * 2]);
                    mma_bf16(d, aPh, &vL[ni][h2 * 2]);
                    mma_bf16(d, aPl, &vH[ni][h2 * 2]);
                }
        }
        __syncthreads();
    }

    // ---- epilogue: normalize, split hi/lo, store (K-major [M][1024]) ----
    const float inv0 = 1.f / lrow[0];
    const float inv1 = 1.f / lrow[1];
    const int row0 = qbase + wm + g;
#pragma unroll
    for (int j = 0; j < 8; ++j) {
        const int col = hcol + j * 8 + tq * 2;
        const float v0 = oacc[j][0] * inv0, v1 = oacc[j][1] * inv0;
        const float v2 = oacc[j][2] * inv1, v3 = oacc[j][3] * inv1;
        const float e0 = __bfloat162float(__float2bfloat16(v0));
        const float e1 = __bfloat162float(__float2bfloat16(v1));
        const float e2 = __bfloat162float(__float2bfloat16(v2));
        const float e3 = __bfloat162float(__float2bfloat16(v3));
        const size_t o0 = (brow + row0) * C_DIM + col;
        const size_t o1 = (brow + row0 + 8) * C_DIM + col;
        *(uint32_t*)&ohi[o0] = pack_bf16(v0, v1);
        *(uint32_t*)&olo[o0] = pack_bf16(v0 - e0, v1 - e1);
        *(uint32_t*)&ohi[o1] = pack_bf16(v2, v3);
        *(uint32_t*)&olo[o1] = pack_bf16(v2 - e2, v3 - e3);
    }
}

// ---------------------------------------------------------------------------
extern "C" void kernel_launch(void* const* d_in, const int* in_sizes, int n_in,
                              void* d_out, int out_size)
{
    const float* x      = (const float*)d_in[0];
    const float* qkv_w  = (const float*)d_in[1];
    const float* qkv_b  = (const float*)d_in[2];
    const float* out_w  = (const float*)d_in[3];
    const float* out_b  = (const float*)d_in[4];
    float* out = (float*)d_out;

    __nv_bfloat16 *qvh, *qvl, *xhi, *xlo, *ahi, *alo, *wqh, *wql, *woh, *wol;
    cudaGetSymbolAddress((void**)&qvh, g_qkvh);
    cudaGetSymbolAddress((void**)&qvl, g_qkvl);
    cudaGetSymbolAddress((void**)&xhi, g_xhi);
    cudaGetSymbolAddress((void**)&xlo, g_xlo);
    cudaGetSymbolAddress((void**)&ahi, g_ahi);
    cudaGetSymbolAddress((void**)&alo, g_alo);
    cudaGetSymbolAddress((void**)&wqh, g_wqt_hi);
    cudaGetSymbolAddress((void**)&wql, g_wqt_lo);
    cudaGetSymbolAddress((void**)&woh, g_wot_hi);
    cudaGetSymbolAddress((void**)&wol, g_wot_lo);

    cudaFuncSetAttribute(gemm_mma, cudaFuncAttributeMaxDynamicSharedMemorySize, SMEM_GEMM);
    cudaFuncSetAttribute(attn_mma, cudaFuncAttributeMaxDynamicSharedMemorySize, SMEM_ATT2);

    // Prepasses: split x; transpose+split weights
    split_k<<<(MTOT * C_DIM / 4 + 255) / 256, 256>>>(x, xhi, xlo, MTOT * C_DIM / 4);
    tsplit_k<<<dim3(C3 / 32, C_DIM / 32), dim3(32, 8)>>>(qkv_w, wqh, wql, C_DIM, C3);
    tsplit_k<<<dim3(C_DIM / 32, C_DIM / 32), dim3(32, 8)>>>(out_w, woh, wol, C_DIM, C_DIM);

    // 1) QKV projection -> split bf16 output (Q pre-scaled by 0.125)
    gemm_mma<<<dim3(C3 / 128, MTOT / 128), 256, SMEM_GEMM>>>(
        xhi, xlo, wqh, wql, qkv_b, nullptr, qvh, qvl, C3, 1);

    // 2) Causal MHA (all-bf16 data path, double-buffered)
    attn_mma<<<dim3(TT / 128, BB * HH), 256, SMEM_ATT2>>>(qvh, qvl, ahi, alo);

    // 3) Output projection -> fp32 final output
    gemm_mma<<<dim3(C_DIM / 128, MTOT / 128), 256, SMEM_GEMM>>>(
        ahi, alo, woh, wol, out_b, out, nullptr, nullptr, C_DIM, 0);
}

// round 7
// speedup vs baseline: 3.0587x; 1.0320x over previous
#include <cuda_runtime.h>
#include <cuda_bf16.h>
#include <cstdint>

#define C_DIM 1024
#define C3    3072
#define BB    2
#define TT    2048
#define HH    16
#define MTOT  4096   // BB*TT

// ---------------------------------------------------------------------------
// Scratch buffers (__device__ globals: the sanctioned no-alloc workaround)
// ---------------------------------------------------------------------------
__device__ __nv_bfloat16 g_qkvh[(size_t)MTOT * C3];     // QKV split hi (Q pre-scaled)
__device__ __nv_bfloat16 g_qkvl[(size_t)MTOT * C3];     // QKV split lo
__device__ __nv_bfloat16 g_xhi[(size_t)MTOT * C_DIM];
__device__ __nv_bfloat16 g_xlo[(size_t)MTOT * C_DIM];
__device__ __nv_bfloat16 g_ahi[(size_t)MTOT * C_DIM];   // attn out hi (K-major)
__device__ __nv_bfloat16 g_alo[(size_t)MTOT * C_DIM];   // attn out lo
__device__ __nv_bfloat16 g_wqt_hi[(size_t)C3 * C_DIM];  // qkv_w^T [N=3072][K=1024]
__device__ __nv_bfloat16 g_wqt_lo[(size_t)C3 * C_DIM];
__device__ __nv_bfloat16 g_wot_hi[(size_t)C_DIM * C_DIM];
__device__ __nv_bfloat16 g_wot_lo[(size_t)C_DIM * C_DIM];

// ---------------------------------------------------------------------------
// Portable tensor-core helpers (compute_103-safe: ldmatrix / mma.sync / cp.async)
// ---------------------------------------------------------------------------
__device__ __forceinline__ uint32_t smem_u32(const void* p) {
    uint32_t a;
    asm("{ .reg .u64 t; cvta.to.shared.u64 t, %1; cvt.u32.u64 %0, t; }"
        : "=r"(a) : "l"(p));
    return a;
}
#define SWZ128(off) ((off) ^ (((off) >> 3) & 0x70))

__device__ __forceinline__ void ldsm4(uint32_t* r, uint32_t addr) {
    asm volatile("ldmatrix.sync.aligned.m8n8.x4.shared.b16 {%0,%1,%2,%3}, [%4];"
        : "=r"(r[0]), "=r"(r[1]), "=r"(r[2]), "=r"(r[3]) : "r"(addr));
}
__device__ __forceinline__ void ldsm4t(uint32_t* r, uint32_t addr) {
    asm volatile("ldmatrix.sync.aligned.m8n8.x4.trans.shared.b16 {%0,%1,%2,%3}, [%4];"
        : "=r"(r[0]), "=r"(r[1]), "=r"(r[2]), "=r"(r[3]) : "r"(addr));
}
__device__ __forceinline__ void mma_bf16(float* d, const uint32_t* a, const uint32_t* b) {
    asm volatile("mma.sync.aligned.m16n8k16.row.col.f32.bf16.bf16.f32 "
        "{%0,%1,%2,%3}, {%4,%5,%6,%7}, {%8,%9}, {%0,%1,%2,%3};"
        : "+f"(d[0]), "+f"(d[1]), "+f"(d[2]), "+f"(d[3])
        : "r"(a[0]), "r"(a[1]), "r"(a[2]), "r"(a[3]), "r"(b[0]), "r"(b[1]));
}
#define CP16(dst, src)  asm volatile("cp.async.cg.shared.global [%0], [%1], 16;" :: "r"(dst), "l"(src) : "memory")
#define CP_COMMIT()     asm volatile("cp.async.commit_group;" ::: "memory")
#define CP_WAIT0()      asm volatile("cp.async.wait_group 0;" ::: "memory")
#define CP_WAIT1()      asm volatile("cp.async.wait_group 1;" ::: "memory")

__device__ __forceinline__ uint32_t pack_bf16(float a, float b) {
    __nv_bfloat162 p;
    p.x = __float2bfloat16(a);
    p.y = __float2bfloat16(b);
    return *(uint32_t*)&p;
}

// ---------------------------------------------------------------------------
// Prepass: fp32 -> (hi, lo) bf16 split.  n4 = element_count/4.
// ---------------------------------------------------------------------------
__global__ __launch_bounds__(256) void split_k(const float* __restrict__ in,
    __nv_bfloat16* __restrict__ hi, __nv_bfloat16* __restrict__ lo, int n4)
{
    const int i = blockIdx.x * 256 + threadIdx.x;
    if (i >= n4) return;
    const float4 v = ((const float4*)in)[i];
    __nv_bfloat16 h0 = __float2bfloat16(v.x), h1 = __float2bfloat16(v.y);
    __nv_bfloat16 h2 = __float2bfloat16(v.z), h3 = __float2bfloat16(v.w);
    __nv_bfloat162 hp0, hp1, lp0, lp1;
    hp0.x = h0; hp0.y = h1; hp1.x = h2; hp1.y = h3;
    lp0.x = __float2bfloat16(v.x - __bfloat162float(h0));
    lp0.y = __float2bfloat16(v.y - __bfloat162float(h1));
    lp1.x = __float2bfloat16(v.z - __bfloat162float(h2));
    lp1.y = __float2bfloat16(v.w - __bfloat162float(h3));
    ((__nv_bfloat162*)hi)[i * 2 + 0] = hp0;
    ((__nv_bfloat162*)hi)[i * 2 + 1] = hp1;
    ((__nv_bfloat162*)lo)[i * 2 + 0] = lp0;
    ((__nv_bfloat162*)lo)[i * 2 + 1] = lp1;
}

// ---------------------------------------------------------------------------
// Prepass: transpose + split.  in [K][N] fp32 -> out hi/lo [N][K] bf16.
// ---------------------------------------------------------------------------
__global__ __launch_bounds__(256) void tsplit_k(const float* __restrict__ in,
    __nv_bfloat16* __restrict__ hiT, __nv_bfloat16* __restrict__ loT, int K, int N)
{
    __shared__ float tile[32][33];
    const int n0 = blockIdx.x * 32, k0 = blockIdx.y * 32;
    const int tx = threadIdx.x, ty = threadIdx.y;
    for (int i = ty; i < 32; i += 8)
        tile[i][tx] = in[(size_t)(k0 + i) * N + n0 + tx];
    __syncthreads();
    for (int i = ty; i < 32; i += 8) {
        const float v = tile[tx][i];
        const __nv_bfloat16 h = __float2bfloat16(v);
        hiT[(size_t)(n0 + i) * K + k0 + tx] = h;
        loT[(size_t)(n0 + i) * K + k0 + tx] = __float2bfloat16(v - __bfloat162float(h));
    }
}

// ---------------------------------------------------------------------------
// mma.sync GEMM v3: C[256x128 per CTA] = A @ B^T + bias.
// Warp tile 64x64 (4M x 2N warps): 16 ldmatrix.x4 per 96 MMAs (6:1).
// BK=64, 2-stage cp.async pipeline; smem 2 x 96KB = 192KB; 1 CTA/SM.
// mode 0: fp32 out.  mode 1: hi/lo bf16 split out, Q block pre-scaled 0.125.
// ---------------------------------------------------------------------------
#define GA_B      32768                  // one A array (256 x 128B)
#define GB_B      16384                  // one B array (128 x 128B)
#define GSTAGE_B  (2 * GA_B + 2 * GB_B)  // 98304
#define SMEM_GEMM (2 * GSTAGE_B)         // 196608

__global__ __launch_bounds__(256, 1) void gemm_mma(
    const __nv_bfloat16* __restrict__ Ahi, const __nv_bfloat16* __restrict__ Alo,
    const __nv_bfloat16* __restrict__ Bhi, const __nv_bfloat16* __restrict__ Blo,
    const float* __restrict__ bias, float* __restrict__ Cf,
    __nv_bfloat16* __restrict__ Chi, __nv_bfloat16* __restrict__ Clo,
    int Ntot, int mode)
{
    extern __shared__ __align__(1024) char smg[];
    const uint32_t sb = smem_u32(smg);
    const int t = threadIdx.x, w = t >> 5, lane = t & 31;
    const int m0 = blockIdx.y << 8, n0 = blockIdx.x << 7;
    const int wm = (w >> 1) << 6, wn = (w & 1) << 6;

    const __nv_bfloat16* srcA[2] = { Ahi + (size_t)m0 * 1024, Alo + (size_t)m0 * 1024 };
    const __nv_bfloat16* srcB[2] = { Bhi + (size_t)n0 * 1024, Blo + (size_t)n0 * 1024 };

    float acc[4][8][4];
#pragma unroll
    for (int i = 0; i < 4; i++)
#pragma unroll
        for (int j = 0; j < 8; j++)
#pragma unroll
            for (int q = 0; q < 4; q++) acc[i][j][q] = 0.f;

    auto fill = [&](int c, int stg) {
        const int k0 = c << 6;
        const uint32_t stb = sb + stg * GSTAGE_B;
#pragma unroll
        for (int arr = 0; arr < 2; ++arr) {          // A hi/lo: 256 rows
            const uint32_t db = stb + arr * GA_B;
            const __nv_bfloat16* s = srcA[arr] + k0;
#pragma unroll
            for (int i = 0; i < 8; ++i) {
                const int idx = t + (i << 8);        // 0..2047
                const int row = idx >> 3, seg = idx & 7;
                CP16(db + SWZ128(row * 128 + seg * 16),
                     s + (size_t)row * 1024 + seg * 8);
            }
        }
#pragma unroll
        for (int arr = 0; arr < 2; ++arr) {          // B hi/lo: 128 rows
            const uint32_t db = stb + 2 * GA_B + arr * GB_B;
            const __nv_bfloat16* s = srcB[arr] + k0;
#pragma unroll
            for (int i = 0; i < 4; ++i) {
                const int idx = t + (i << 8);        // 0..1023
                const int row = idx >> 3, seg = idx & 7;
                CP16(db + SWZ128(row * 128 + seg * 16),
                     s + (size_t)row * 1024 + seg * 8);
            }
        }
    };

    fill(0, 0);
    CP_COMMIT();
    CP_WAIT0();
    __syncthreads();

    const int aRow = wm + (lane & 15);
    const int bRow = wn + ((lane >> 4) << 3) + (lane & 7);

    for (int c = 0; c < 16; ++c) {
        const int stg = c & 1;
        if (c < 15) { fill(c + 1, stg ^ 1); CP_COMMIT(); }

        const uint32_t stA_h = sb + stg * GSTAGE_B;
        const uint32_t stA_l = stA_h + GA_B;
        const uint32_t stB_h = stA_h + 2 * GA_B;
        const uint32_t stB_l = stB_h + GB_B;

#pragma unroll
        for (int k16 = 0; k16 < 4; ++k16) {
            const int kbA = k16 * 32 + ((lane >> 4) & 1) * 16;
            const int kbB = k16 * 32 + ((lane >> 3) & 1) * 16;

            uint32_t aH[4][4], aL[4][4];
#pragma unroll
            for (int mi = 0; mi < 4; ++mi) {
                const uint32_t off = SWZ128((aRow + mi * 16) * 128 + kbA);
                ldsm4(aH[mi], stA_h + off);
                ldsm4(aL[mi], stA_l + off);
            }
            uint32_t bH[4][4], bL[4][4];
#pragma unroll
            for (int ni = 0; ni < 4; ++ni) {
                const uint32_t off = SWZ128((bRow + ni * 16) * 128 + kbB);
                ldsm4(bH[ni], stB_h + off);
                ldsm4(bL[ni], stB_l + off);
            }
#pragma unroll
            for (int mi = 0; mi < 4; ++mi)
#pragma unroll
                for (int ni = 0; ni < 4; ++ni)
#pragma unroll
                    for (int h2 = 0; h2 < 2; ++h2) {
                        float* d = acc[mi][ni * 2 + h2];
                        mma_bf16(d, aH[mi], &bH[ni][h2 * 2]);
                        mma_bf16(d, aH[mi], &bL[ni][h2 * 2]);
                        mma_bf16(d, aL[mi], &bH[ni][h2 * 2]);
                    }
        }
        CP_WAIT0();
        __syncthreads();
    }

    const int g2 = lane >> 2, tg = lane & 3;
    if (mode == 0) {
#pragma unroll
        for (int mi = 0; mi < 4; ++mi) {
            const int row0 = m0 + wm + mi * 16 + g2;
#pragma unroll
            for (int j = 0; j < 8; ++j) {
                const int col = n0 + wn + j * 8 + tg * 2;
                const float2 b2 = *(const float2*)&bias[col];
                const float* d = acc[mi][j];
                float2 lo2 = { d[0] + b2.x, d[1] + b2.y };
                float2 hi2 = { d[2] + b2.x, d[3] + b2.y };
                *(float2*)&Cf[(size_t)row0 * Ntot + col] = lo2;
                *(float2*)&Cf[(size_t)(row0 + 8) * Ntot + col] = hi2;
            }
        }
    } else {
        const float scale = (n0 < C_DIM) ? 0.125f : 1.0f;   // Q block pre-scale
#pragma unroll
        for (int mi = 0; mi < 4; ++mi) {
            const int row0 = m0 + wm + mi * 16 + g2;
#pragma unroll
            for (int j = 0; j < 8; ++j) {
                const int col = n0 + wn + j * 8 + tg * 2;
                const float2 b2 = *(const float2*)&bias[col];
                const float* d = acc[mi][j];
                const float v0 = (d[0] + b2.x) * scale, v1 = (d[1] + b2.y) * scale;
                const float v2 = (d[2] + b2.x) * scale, v3 = (d[3] + b2.y) * scale;
                const float e0 = __bfloat162float(__float2bfloat16(v0));
                const float e1 = __bfloat162float(__float2bfloat16(v1));
                const float e2 = __bfloat162float(__float2bfloat16(v2));
                const float e3 = __bfloat162float(__float2bfloat16(v3));
                const size_t o0 = (size_t)row0 * Ntot + col;
                const size_t o1 = (size_t)(row0 + 8) * Ntot + col;
                *(uint32_t*)&Chi[o0] = pack_bf16(v0, v1);
                *(uint32_t*)&Clo[o0] = pack_bf16(v0 - e0, v1 - e1);
                *(uint32_t*)&Chi[o1] = pack_bf16(v2, v3);
                *(uint32_t*)&Clo[o1] = pack_bf16(v2 - e2, v3 - e3);
            }
        }
    }
}

// ---------------------------------------------------------------------------
// Flash attention (unchanged from R6 passing kernel): all-bf16-split inputs via
// cp.async, double-buffered K/V, Q frags hoisted, V row-major + ldmatrix.trans.
// ---------------------------------------------------------------------------
#define SMEM_ATT2 98304

__global__ __launch_bounds__(256) void attn_mma(
    const __nv_bfloat16* __restrict__ qh, const __nv_bfloat16* __restrict__ ql,
    __nv_bfloat16* __restrict__ ohi, __nv_bfloat16* __restrict__ olo)
{
    extern __shared__ __align__(1024) char sma[];
    const uint32_t sb  = smem_u32(sma);
    const uint32_t sQh = sb, sQl = sb + 16384;

    const int t = threadIdx.x, w = t >> 5, lane = t & 31;
    const int g = lane >> 2, tq = lane & 3;
    const int qi = gridDim.x - 1 - blockIdx.x;      // heavy tiles first
    const int bh = blockIdx.y, b = bh >> 4, h = bh & 15;
    const int qbase = qi << 7;
    const size_t brow = (size_t)b * TT;
    const int wm = w << 4;
    const int hcol = h * 64;

    auto fillQ = [&]() {
#pragma unroll
        for (int i = 0; i < 8; ++i) {
            const int idx = t + (i << 8);            // 0..2047
            const int arr = idx >> 10;               // 0 hi, 1 lo
            const int r = (idx >> 3) & 127, seg = idx & 7;
            const __nv_bfloat16* src =
                (arr ? ql : qh) + (brow + qbase + r) * C3 + hcol + seg * 8;
            CP16((arr ? sQl : sQh) + SWZ128(r * 128 + seg * 16), src);
        }
    };
    auto fillKV = [&](int kt, int buf) {
        const int kb = kt << 6;
        const uint32_t sbase = sb + 32768 + buf * 32768;
#pragma unroll
        for (int i = 0; i < 8; ++i) {
            const int idx = t + (i << 8);            // 0..2047
            const int arr = idx >> 9;                // 0 Kh, 1 Kl, 2 Vh, 3 Vl
            const int r = (idx >> 3) & 63, seg = idx & 7;
            const int colbase = ((arr < 2) ? C_DIM : 2 * C_DIM) + hcol;
            const __nv_bfloat16* src =
                ((arr & 1) ? ql : qh) + (brow + kb + r) * C3 + colbase + seg * 8;
            CP16(sbase + arr * 8192 + SWZ128(r * 128 + seg * 16), src);
        }
    };

    float oacc[8][4];
#pragma unroll
    for (int j = 0; j < 8; ++j)
#pragma unroll
        for (int q = 0; q < 4; ++q) oacc[j][q] = 0.f;
    float mrow[2] = { -1e30f, -1e30f };
    float lrow[2] = { 0.f, 0.f };

    const int aRow  = wm + (lane & 15);
    const int bRowS = ((lane >> 4) << 3) + (lane & 7);
    const int ntiles = 2 * qi + 2;

    uint32_t aQh[4][4], aQl[4][4];                   // Q frags, hoisted

    fillQ();
    fillKV(0, 0);
    CP_COMMIT();

    for (int kt = 0; kt < ntiles; ++kt) {
        const int kb = kt << 6;
        const uint32_t sKh = sb + 32768 + (kt & 1) * 32768;
        const uint32_t sKl = sKh + 8192, sVh = sKh + 16384, sVl = sKh + 24576;

        if (kt + 1 < ntiles) {
            fillKV(kt + 1, (kt + 1) & 1);
            CP_COMMIT();
            CP_WAIT1();
        } else {
            CP_WAIT0();
        }
        __syncthreads();

        if (kt == 0) {
#pragma unroll
            for (int k16 = 0; k16 < 4; ++k16) {
                const int kbA = k16 * 32 + ((lane >> 4) & 1) * 16;
                const uint32_t offA = SWZ128(aRow * 128 + kbA);
                ldsm4(aQh[k16], sQh + offA);
                ldsm4(aQl[k16], sQl + offA);
            }
        }

        // ---- S = Q K^T (split, fp32 accum) ----
        float sacc[8][4];
#pragma unroll
        for (int j = 0; j < 8; ++j)
#pragma unroll
            for (int q = 0; q < 4; ++q) sacc[j][q] = 0.f;

#pragma unroll
        for (int k16 = 0; k16 < 4; ++k16) {
            const int kbB = k16 * 32 + ((lane >> 3) & 1) * 16;
            uint32_t bH[4][4], bL[4][4];
#pragma unroll
            for (int ni = 0; ni < 4; ++ni) {
                const uint32_t off = SWZ128((bRowS + ni * 16) * 128 + kbB);
                ldsm4(bH[ni], sKh + off);
                ldsm4(bL[ni], sKl + off);
            }
#pragma unroll
            for (int ni = 0; ni < 4; ++ni)
#pragma unroll
                for (int h2 = 0; h2 < 2; ++h2) {
                    float* d = sacc[ni * 2 + h2];
                    mma_bf16(d, aQh[k16], &bH[ni][h2 * 2]);
                    mma_bf16(d, aQh[k16], &bL[ni][h2 * 2]);
                    mma_bf16(d, aQl[k16], &bH[ni][h2 * 2]);
                }
        }

        // ---- causal mask (only last two tiles cross the diagonal) ----
        if (kt >= 2 * qi) {
            const int row0 = qbase + wm + g;
#pragma unroll
            for (int j = 0; j < 8; ++j) {
                const int col = kb + j * 8 + tq * 2;
                if (col     > row0)     sacc[j][0] = -1e30f;
                if (col + 1 > row0)     sacc[j][1] = -1e30f;
                if (col     > row0 + 8) sacc[j][2] = -1e30f;
                if (col + 1 > row0 + 8) sacc[j][3] = -1e30f;
            }
        }

        // ---- online softmax (2 rows/thread, quad reductions) ----
#pragma unroll
        for (int rr = 0; rr < 2; ++rr) {
            const int i0 = rr * 2;
            float mt = -1e30f;
#pragma unroll
            for (int j = 0; j < 8; ++j)
                mt = fmaxf(mt, fmaxf(sacc[j][i0], sacc[j][i0 + 1]));
            mt = fmaxf(mt, __shfl_xor_sync(0xffffffffu, mt, 1));
            mt = fmaxf(mt, __shfl_xor_sync(0xffffffffu, mt, 2));
            const float mn = fmaxf(mrow[rr], mt);
            const float alpha = __expf(mrow[rr] - mn);
            mrow[rr] = mn;
            float ps = 0.f;
#pragma unroll
            for (int j = 0; j < 8; ++j) {
                const float p0 = __expf(sacc[j][i0] - mn);
                const float p1 = __expf(sacc[j][i0 + 1] - mn);
                sacc[j][i0] = p0; sacc[j][i0 + 1] = p1;
                ps += p0 + p1;
            }
            ps += __shfl_xor_sync(0xffffffffu, ps, 1);
            ps += __shfl_xor_sync(0xffffffffu, ps, 2);
            lrow[rr] = lrow[rr] * alpha + ps;
#pragma unroll
            for (int j = 0; j < 8; ++j) {
                oacc[j][i0] *= alpha;
                oacc[j][i0 + 1] *= alpha;
            }
        }

        // ---- O += P V (P split register-direct; V via ldmatrix.trans) ----
#pragma unroll
        for (int kk = 0; kk < 4; ++kk) {
            const float* s0 = sacc[2 * kk];
            const float* s1 = sacc[2 * kk + 1];
            uint32_t aPh[4], aPl[4];
            {
                float h00 = __bfloat162float(__float2bfloat16(s0[0]));
                float h01 = __bfloat162float(__float2bfloat16(s0[1]));
                float h02 = __bfloat162float(__float2bfloat16(s0[2]));
                float h03 = __bfloat162float(__float2bfloat16(s0[3]));
                float h10 = __bfloat162float(__float2bfloat16(s1[0]));
                float h11 = __bfloat162float(__float2bfloat16(s1[1]));
                float h12 = __bfloat162float(__float2bfloat16(s1[2]));
                float h13 = __bfloat162float(__float2bfloat16(s1[3]));
                aPh[0] = pack_bf16(s0[0], s0[1]);
                aPh[1] = pack_bf16(s0[2], s0[3]);
                aPh[2] = pack_bf16(s1[0], s1[1]);
                aPh[3] = pack_bf16(s1[2], s1[3]);
                aPl[0] = pack_bf16(s0[0] - h00, s0[1] - h01);
                aPl[1] = pack_bf16(s0[2] - h02, s0[3] - h03);
                aPl[2] = pack_bf16(s1[0] - h10, s1[1] - h11);
                aPl[3] = pack_bf16(s1[2] - h12, s1[3] - h13);
            }
            const int vr = kk * 16 + (lane & 15);
            const int vc = ((lane >> 4) & 1) * 16;
            uint32_t vH[4][4], vL[4][4];
#pragma unroll
            for (int ni = 0; ni < 4; ++ni) {
                const uint32_t off = SWZ128(vr * 128 + ni * 32 + vc);
                ldsm4t(vH[ni], sVh + off);
                ldsm4t(vL[ni], sVl + off);
            }
#pragma unroll
            for (int ni = 0; ni < 4; ++ni)
#pragma unroll
                for (int h2 = 0; h2 < 2; ++h2) {
                    float* d = oacc[ni * 2 + h2];
                    mma_bf16(d, aPh, &vH[ni][h2 * 2]);
                    mma_bf16(d, aPh, &vL[ni][h2 * 2]);
                    mma_bf16(d, aPl, &vH[ni][h2 * 2]);
                }
        }
        __syncthreads();
    }

    // ---- epilogue: normalize, split hi/lo, store (K-major [M][1024]) ----
    const float inv0 = 1.f / lrow[0];
    const float inv1 = 1.f / lrow[1];
    const int row0 = qbase + wm + g;
#pragma unroll
    for (int j = 0; j < 8; ++j) {
        const int col = hcol + j * 8 + tq * 2;
        const float v0 = oacc[j][0] * inv0, v1 = oacc[j][1] * inv0;
        const float v2 = oacc[j][2] * inv1, v3 = oacc[j][3] * inv1;
        const float e0 = __bfloat162float(__float2bfloat16(v0));
        const float e1 = __bfloat162float(__float2bfloat16(v1));
        const float e2 = __bfloat162float(__float2bfloat16(v2));
        const float e3 = __bfloat162float(__float2bfloat16(v3));
        const size_t o0 = (brow + row0) * C_DIM + col;
        const size_t o1 = (brow + row0 + 8) * C_DIM + col;
        *(uint32_t*)&ohi[o0] = pack_bf16(v0, v1);
        *(uint32_t*)&olo[o0] = pack_bf16(v0 - e0, v1 - e1);
        *(uint32_t*)&ohi[o1] = pack_bf16(v2, v3);
        *(uint32_t*)&olo[o1] = pack_bf16(v2 - e2, v3 - e3);
    }
}

// ---------------------------------------------------------------------------
extern "C" void kernel_launch(void* const* d_in, const int* in_sizes, int n_in,
                              void* d_out, int out_size)
{
    const float* x      = (const float*)d_in[0];
    const float* qkv_w  = (const float*)d_in[1];
    const float* qkv_b  = (const float*)d_in[2];
    const float* out_w  = (const float*)d_in[3];
    const float* out_b  = (const float*)d_in[4];
    float* out = (float*)d_out;

    __nv_bfloat16 *qvh, *qvl, *xhi, *xlo, *ahi, *alo, *wqh, *wql, *woh, *wol;
    cudaGetSymbolAddress((void**)&qvh, g_qkvh);
    cudaGetSymbolAddress((void**)&qvl, g_qkvl);
    cudaGetSymbolAddress((void**)&xhi, g_xhi);
    cudaGetSymbolAddress((void**)&xlo, g_xlo);
    cudaGetSymbolAddress((void**)&ahi, g_ahi);
    cudaGetSymbolAddress((void**)&alo, g_alo);
    cudaGetSymbolAddress((void**)&wqh, g_wqt_hi);
    cudaGetSymbolAddress((void**)&wql, g_wqt_lo);
    cudaGetSymbolAddress((void**)&woh, g_wot_hi);
    cudaGetSymbolAddress((void**)&wol, g_wot_lo);

    cudaFuncSetAttribute(gemm_mma, cudaFuncAttributeMaxDynamicSharedMemorySize, SMEM_GEMM);
    cudaFuncSetAttribute(attn_mma, cudaFuncAttributeMaxDynamicSharedMemorySize, SMEM_ATT2);

    // Prepasses: split x; transpose+split weights
    split_k<<<(MTOT * C_DIM / 4 + 255) / 256, 256>>>(x, xhi, xlo, MTOT * C_DIM / 4);
    tsplit_k<<<dim3(C3 / 32, C_DIM / 32), dim3(32, 8)>>>(qkv_w, wqh, wql, C_DIM, C3);
    tsplit_k<<<dim3(C_DIM / 32, C_DIM / 32), dim3(32, 8)>>>(out_w, woh, wol, C_DIM, C_DIM);

    // 1) QKV projection -> split bf16 output (Q pre-scaled by 0.125)
    gemm_mma<<<dim3(C3 / 128, MTOT / 256), 256, SMEM_GEMM>>>(
        xhi, xlo, wqh, wql, qkv_b, nullptr, qvh, qvl, C3, 1);

    // 2) Causal MHA (all-bf16 data path, double-buffered)
    attn_mma<<<dim3(TT / 128, BB * HH), 256, SMEM_ATT2>>>(qvh, qvl, ahi, alo);

    // 3) Output projection -> fp32 final output
    gemm_mma<<<dim3(C_DIM / 128, MTOT / 256), 256, SMEM_GEMM>>>(
        ahi, alo, woh, wol, out_b, out, nullptr, nullptr, C_DIM, 0);
}